// round 1
// baseline (speedup 1.0000x reference)
#include <cuda_runtime.h>
#include <math.h>

#define BATCH 2
#define C     192
#define S     32768
#define NH    8
#define DH    64
#define INNER 512
#define ATT_SCALE 0.125f
#define GCHUNKS 8

// ---------------- device scratch (static, no allocation) ----------------
__device__ float g_Gpart[BATCH * GCHUNKS * C * C];   // partial grams
__device__ float g_G[BATCH * C * C];                 // G = X X^T  [b][c][d]
__device__ float g_T[BATCH * INNER * C];             // T = Wq @ G [b][o][d]
__device__ float g_attn[BATCH * NH * DH * DH];       // softmax(sim)
__device__ float g_AV[BATCH * INNER * C];            // blockdiag(attn) @ Wv
__device__ float g_Mpart[BATCH * 4 * C * C];         // partial M = Wo @ AV
__device__ float g_M[BATCH * C * C];                 // final M

// ---------------- K1: G = X X^T (split-K partials) ----------------
// grid: (9 tiles * GCHUNKS, BATCH), 256 threads. 64x64 tile, 4x4 per thread.
__global__ void k_gram(const float* __restrict__ x) {
    int tile  = blockIdx.x / GCHUNKS;
    int chunk = blockIdx.x % GCHUNKS;
    int b = blockIdx.y;
    int i0 = (tile / 3) * 64;
    int j0 = (tile % 3) * 64;
    const float* xb = x + (size_t)b * C * S;

    __shared__ float As[64][68];
    __shared__ float Bs[64][68];

    int tid = threadIdx.x;
    int tx = tid & 15, ty = tid >> 4;
    float acc[4][4] = {};

    const int SPB = S / GCHUNKS;          // 4096
    int sbeg = chunk * SPB;

    for (int st = 0; st < SPB; st += 64) {
        int sb = sbeg + st;
        #pragma unroll
        for (int l = 0; l < 16; l++) {
            int idx = tid + l * 256;
            int r = idx >> 6, q = idx & 63;
            As[r][q] = xb[(size_t)(i0 + r) * S + sb + q];
            Bs[r][q] = xb[(size_t)(j0 + r) * S + sb + q];
        }
        __syncthreads();
        #pragma unroll 4
        for (int s = 0; s < 64; s += 4) {
            float4 av[4], bv[4];
            #pragma unroll
            for (int k = 0; k < 4; k++) {
                av[k] = *reinterpret_cast<const float4*>(&As[ty * 4 + k][s]);
                bv[k] = *reinterpret_cast<const float4*>(&Bs[tx * 4 + k][s]);
            }
            #pragma unroll
            for (int ii = 0; ii < 4; ii++)
                #pragma unroll
                for (int jj = 0; jj < 4; jj++)
                    acc[ii][jj] += av[ii].x * bv[jj].x + av[ii].y * bv[jj].y
                                 + av[ii].z * bv[jj].z + av[ii].w * bv[jj].w;
        }
        __syncthreads();
    }

    float* Gp = g_Gpart + ((size_t)(b * GCHUNKS + chunk)) * C * C;
    #pragma unroll
    for (int ii = 0; ii < 4; ii++)
        #pragma unroll
        for (int jj = 0; jj < 4; jj++)
            Gp[(i0 + ty * 4 + ii) * C + j0 + tx * 4 + jj] = acc[ii][jj];
}

__global__ void k_gram_reduce() {
    int b = blockIdx.y;
    int e = blockIdx.x * 256 + threadIdx.x;
    if (e < C * C) {
        float s = 0.f;
        #pragma unroll
        for (int ch = 0; ch < GCHUNKS; ch++)
            s += g_Gpart[((size_t)(b * GCHUNKS + ch)) * C * C + e];
        g_G[(size_t)b * C * C + e] = s;
    }
}

// ---------------- K2a: T = Wq @ G  [512x192] ----------------
// grid: (3 d-tiles, 8 o-tiles, BATCH), 256 threads, 64x64 tile, 4x4 per thread.
__global__ void k_qg(const float* __restrict__ wq) {
    int d0 = blockIdx.x * 64;
    int o0 = blockIdx.y * 64;
    int b  = blockIdx.z;

    __shared__ float Ws[64][68];  // [o_local][c_local]
    __shared__ float Gs[64][68];  // [c_local][d_local]

    int tid = threadIdx.x;
    int tx = tid & 15, ty = tid >> 4;
    float acc[4][4] = {};
    const float* Gb = g_G + (size_t)b * C * C;

    for (int c0 = 0; c0 < C; c0 += 64) {
        #pragma unroll
        for (int l = 0; l < 16; l++) {
            int idx = tid + l * 256;
            int r = idx >> 6, q = idx & 63;
            Ws[r][q] = wq[(o0 + r) * C + c0 + q];
            Gs[r][q] = Gb[(c0 + r) * C + d0 + q];
        }
        __syncthreads();
        #pragma unroll 16
        for (int c = 0; c < 64; c++) {
            float4 gv = *reinterpret_cast<const float4*>(&Gs[c][tx * 4]);
            float w0 = Ws[ty * 4 + 0][c], w1 = Ws[ty * 4 + 1][c];
            float w2 = Ws[ty * 4 + 2][c], w3 = Ws[ty * 4 + 3][c];
            acc[0][0] += w0 * gv.x; acc[0][1] += w0 * gv.y; acc[0][2] += w0 * gv.z; acc[0][3] += w0 * gv.w;
            acc[1][0] += w1 * gv.x; acc[1][1] += w1 * gv.y; acc[1][2] += w1 * gv.z; acc[1][3] += w1 * gv.w;
            acc[2][0] += w2 * gv.x; acc[2][1] += w2 * gv.y; acc[2][2] += w2 * gv.z; acc[2][3] += w2 * gv.w;
            acc[3][0] += w3 * gv.x; acc[3][1] += w3 * gv.y; acc[3][2] += w3 * gv.z; acc[3][3] += w3 * gv.w;
        }
        __syncthreads();
    }
    float* Tb = g_T + (size_t)b * INNER * C;
    #pragma unroll
    for (int ii = 0; ii < 4; ii++)
        #pragma unroll
        for (int jj = 0; jj < 4; jj++)
            Tb[(o0 + ty * 4 + ii) * C + d0 + tx * 4 + jj] = acc[ii][jj];
}

// ---------------- K2b: sim = SCALE * T_n @ Wk_n^T, softmax -> attn ----------------
// grid: (NH, BATCH), 256 threads. Full 64x64 sim per block.
__global__ void k_sim_softmax(const float* __restrict__ wk) {
    int n = blockIdx.x, b = blockIdx.y;
    __shared__ float buf[2 * 64 * 68];
    float (*Ts)[68] = (float (*)[68])buf;
    float (*Ks)[68] = (float (*)[68])(buf + 64 * 68);

    int tid = threadIdx.x;
    int tx = tid & 15, ty = tid >> 4;
    float acc[4][4] = {};

    const float* Tb = g_T + ((size_t)b * INNER + (size_t)n * DH) * C;
    const float* Kb = wk + (size_t)n * DH * C;

    for (int d0 = 0; d0 < C; d0 += 64) {
        #pragma unroll
        for (int l = 0; l < 16; l++) {
            int idx = tid + l * 256;
            int r = idx >> 6, q = idx & 63;
            Ts[r][q] = Tb[r * C + d0 + q];
            Ks[r][q] = Kb[r * C + d0 + q];
        }
        __syncthreads();
        #pragma unroll 4
        for (int s = 0; s < 64; s += 4) {
            float4 av[4], bv[4];
            #pragma unroll
            for (int k = 0; k < 4; k++) {
                av[k] = *reinterpret_cast<const float4*>(&Ts[ty * 4 + k][s]);
                bv[k] = *reinterpret_cast<const float4*>(&Ks[tx * 4 + k][s]);
            }
            #pragma unroll
            for (int ii = 0; ii < 4; ii++)
                #pragma unroll
                for (int jj = 0; jj < 4; jj++)
                    acc[ii][jj] += av[ii].x * bv[jj].x + av[ii].y * bv[jj].y
                                 + av[ii].z * bv[jj].z + av[ii].w * bv[jj].w;
        }
        __syncthreads();
    }

    // write sim to smem (reuse buf)
    float (*sims)[65] = (float (*)[65])buf;
    #pragma unroll
    for (int ii = 0; ii < 4; ii++)
        #pragma unroll
        for (int jj = 0; jj < 4; jj++)
            sims[ty * 4 + ii][tx * 4 + jj] = acc[ii][jj] * ATT_SCALE;
    __syncthreads();

    // softmax over rows (each warp handles rows w, w+8, ...)
    int w = tid >> 5, lane = tid & 31;
    for (int r = w; r < 64; r += 8) {
        float m = fmaxf(sims[r][lane], sims[r][lane + 32]);
        #pragma unroll
        for (int off = 16; off; off >>= 1)
            m = fmaxf(m, __shfl_xor_sync(0xffffffffu, m, off));
        float e0 = expf(sims[r][lane] - m);
        float e1 = expf(sims[r][lane + 32] - m);
        float sum = e0 + e1;
        #pragma unroll
        for (int off = 16; off; off >>= 1)
            sum += __shfl_xor_sync(0xffffffffu, sum, off);
        float inv = 1.f / sum;
        float* arow = g_attn + (((size_t)(b * NH + n)) * DH + r) * DH;
        arow[lane]      = e0 * inv;
        arow[lane + 32] = e1 * inv;
    }
}

// ---------------- K3a: AV[b][n*64+i][c] = sum_j attn[i][j] * Wv[n*64+j][c] ----------------
// grid: (3 c-tiles, NH, BATCH), 256 threads.
__global__ void k_av(const float* __restrict__ wv) {
    int c0 = blockIdx.x * 64;
    int n  = blockIdx.y;
    int b  = blockIdx.z;

    __shared__ float Asm[64][68];  // attn [i][j]
    __shared__ float Vs[64][68];   // wv   [j][c_local]

    int tid = threadIdx.x;
    int tx = tid & 15, ty = tid >> 4;

    #pragma unroll
    for (int l = 0; l < 16; l++) {
        int idx = tid + l * 256;
        int r = idx >> 6, q = idx & 63;
        Asm[r][q] = g_attn[(((size_t)(b * NH + n)) * DH + r) * DH + q];
        Vs[r][q]  = wv[(n * DH + r) * C + c0 + q];
    }
    __syncthreads();

    float acc[4][4] = {};
    #pragma unroll 16
    for (int j = 0; j < 64; j++) {
        float4 vv = *reinterpret_cast<const float4*>(&Vs[j][tx * 4]);
        float a0 = Asm[ty * 4 + 0][j], a1 = Asm[ty * 4 + 1][j];
        float a2 = Asm[ty * 4 + 2][j], a3 = Asm[ty * 4 + 3][j];
        acc[0][0] += a0 * vv.x; acc[0][1] += a0 * vv.y; acc[0][2] += a0 * vv.z; acc[0][3] += a0 * vv.w;
        acc[1][0] += a1 * vv.x; acc[1][1] += a1 * vv.y; acc[1][2] += a1 * vv.z; acc[1][3] += a1 * vv.w;
        acc[2][0] += a2 * vv.x; acc[2][1] += a2 * vv.y; acc[2][2] += a2 * vv.z; acc[2][3] += a2 * vv.w;
        acc[3][0] += a3 * vv.x; acc[3][1] += a3 * vv.y; acc[3][2] += a3 * vv.z; acc[3][3] += a3 * vv.w;
    }
    #pragma unroll
    for (int ii = 0; ii < 4; ii++)
        #pragma unroll
        for (int jj = 0; jj < 4; jj++)
            g_AV[((size_t)b * INNER + n * DH + ty * 4 + ii) * C + c0 + tx * 4 + jj] = acc[ii][jj];
}

// ---------------- K3b: Mpart = Wo @ AV (k-split 4) ----------------
// grid: (3 c-tiles, 3 o-tiles * 4 k-splits, BATCH), 256 threads.
__global__ void k_m(const float* __restrict__ wo) {
    int c0 = blockIdx.x * 64;
    int o0 = (blockIdx.y % 3) * 64;
    int kc = blockIdx.y / 3;          // 0..3
    int b  = blockIdx.z;

    __shared__ float Ws[64][68];  // wo [o_local][k_local]
    __shared__ float Vs[64][68];  // AV [k_local][c_local]

    int tid = threadIdx.x;
    int tx = tid & 15, ty = tid >> 4;
    float acc[4][4] = {};

    for (int kk = 0; kk < 128; kk += 64) {
        int k0 = kc * 128 + kk;
        #pragma unroll
        for (int l = 0; l < 16; l++) {
            int idx = tid + l * 256;
            int r = idx >> 6, q = idx & 63;
            Ws[r][q] = wo[(o0 + r) * INNER + k0 + q];
            Vs[r][q] = g_AV[((size_t)b * INNER + k0 + r) * C + c0 + q];
        }
        __syncthreads();
        #pragma unroll 16
        for (int k = 0; k < 64; k++) {
            float4 vv = *reinterpret_cast<const float4*>(&Vs[k][tx * 4]);
            float w0 = Ws[ty * 4 + 0][k], w1 = Ws[ty * 4 + 1][k];
            float w2 = Ws[ty * 4 + 2][k], w3 = Ws[ty * 4 + 3][k];
            acc[0][0] += w0 * vv.x; acc[0][1] += w0 * vv.y; acc[0][2] += w0 * vv.z; acc[0][3] += w0 * vv.w;
            acc[1][0] += w1 * vv.x; acc[1][1] += w1 * vv.y; acc[1][2] += w1 * vv.z; acc[1][3] += w1 * vv.w;
            acc[2][0] += w2 * vv.x; acc[2][1] += w2 * vv.y; acc[2][2] += w2 * vv.z; acc[2][3] += w2 * vv.w;
            acc[3][0] += w3 * vv.x; acc[3][1] += w3 * vv.y; acc[3][2] += w3 * vv.z; acc[3][3] += w3 * vv.w;
        }
        __syncthreads();
    }
    float* Mp = g_Mpart + ((size_t)(b * 4 + kc)) * C * C;
    #pragma unroll
    for (int ii = 0; ii < 4; ii++)
        #pragma unroll
        for (int jj = 0; jj < 4; jj++)
            Mp[(o0 + ty * 4 + ii) * C + c0 + tx * 4 + jj] = acc[ii][jj];
}

__global__ void k_m_reduce() {
    int b = blockIdx.y;
    int e = blockIdx.x * 256 + threadIdx.x;
    if (e < C * C) {
        float s = 0.f;
        #pragma unroll
        for (int kc = 0; kc < 4; kc++)
            s += g_Mpart[((size_t)(b * 4 + kc)) * C * C + e];
        g_M[(size_t)b * C * C + e] = s;
    }
}

// ---------------- K4: out = M @ X + bo ----------------
// grid: (512 s-tiles, 3 o-tiles, BATCH), 256 threads, 64x64 tile, 4x4 per thread.
__global__ void k_out(const float* __restrict__ x, const float* __restrict__ bo,
                      float* __restrict__ out) {
    int s0 = blockIdx.x * 64;
    int o0 = blockIdx.y * 64;
    int b  = blockIdx.z;

    __shared__ float Ms[64][68];  // M [o_local][c_local]
    __shared__ float Xs[64][68];  // X [c_local][s_local]

    int tid = threadIdx.x;
    int tx = tid & 15, ty = tid >> 4;
    float acc[4][4] = {};
    const float* xb = x + (size_t)b * C * S;
    const float* Mb = g_M + (size_t)b * C * C;

    for (int c0 = 0; c0 < C; c0 += 64) {
        #pragma unroll
        for (int l = 0; l < 16; l++) {
            int idx = tid + l * 256;
            int r = idx >> 6, q = idx & 63;
            Ms[r][q] = Mb[(o0 + r) * C + c0 + q];
            Xs[r][q] = xb[(size_t)(c0 + r) * S + s0 + q];
        }
        __syncthreads();
        #pragma unroll 16
        for (int c = 0; c < 64; c++) {
            float4 xv = *reinterpret_cast<const float4*>(&Xs[c][tx * 4]);
            float m0 = Ms[ty * 4 + 0][c], m1 = Ms[ty * 4 + 1][c];
            float m2 = Ms[ty * 4 + 2][c], m3 = Ms[ty * 4 + 3][c];
            acc[0][0] += m0 * xv.x; acc[0][1] += m0 * xv.y; acc[0][2] += m0 * xv.z; acc[0][3] += m0 * xv.w;
            acc[1][0] += m1 * xv.x; acc[1][1] += m1 * xv.y; acc[1][2] += m1 * xv.z; acc[1][3] += m1 * xv.w;
            acc[2][0] += m2 * xv.x; acc[2][1] += m2 * xv.y; acc[2][2] += m2 * xv.z; acc[2][3] += m2 * xv.w;
            acc[3][0] += m3 * xv.x; acc[3][1] += m3 * xv.y; acc[3][2] += m3 * xv.z; acc[3][3] += m3 * xv.w;
        }
        __syncthreads();
    }

    #pragma unroll
    for (int ii = 0; ii < 4; ii++) {
        int o = o0 + ty * 4 + ii;
        float bias = bo[o];
        float4 r;
        r.x = acc[ii][0] + bias;
        r.y = acc[ii][1] + bias;
        r.z = acc[ii][2] + bias;
        r.w = acc[ii][3] + bias;
        *reinterpret_cast<float4*>(&out[((size_t)b * C + o) * S + s0 + tx * 4]) = r;
    }
}

// ---------------- launch ----------------
extern "C" void kernel_launch(void* const* d_in, const int* in_sizes, int n_in,
                              void* d_out, int out_size) {
    const float* x  = (const float*)d_in[0];
    const float* wq = (const float*)d_in[1];
    const float* wk = (const float*)d_in[2];
    const float* wv = (const float*)d_in[3];
    const float* wo = (const float*)d_in[4];
    const float* bo = (const float*)d_in[5];
    float* out = (float*)d_out;

    k_gram<<<dim3(9 * GCHUNKS, BATCH), 256>>>(x);
    k_gram_reduce<<<dim3(144, BATCH), 256>>>();
    k_qg<<<dim3(3, 8, BATCH), 256>>>(wq);
    k_sim_softmax<<<dim3(NH, BATCH), 256>>>(wk);
    k_av<<<dim3(3, NH, BATCH), 256>>>(wv);
    k_m<<<dim3(3, 12, BATCH), 256>>>(wo);
    k_m_reduce<<<dim3(144, BATCH), 256>>>();
    k_out<<<dim3(512, 3, BATCH), 256>>>(x, bo, out);
}

// round 2
// speedup vs baseline: 1.8525x; 1.8525x over previous
#include <cuda_runtime.h>
#include <cuda_bf16.h>
#include <math.h>
#include <stdint.h>

#define BATCH 2
#define C     192
#define S     32768
#define NH    8
#define DH    64
#define INNER 512
#define ATT_SCALE 0.125f
#define GC    32            // gram split-K chunks
#define SPB   (S / GC)      // 1024 spatial per chunk

// ---------------- device scratch (static, no allocation) ----------------
__device__ float g_Gpart[BATCH * GC * 6 * 64 * 64]; // upper-tri tile partials
__device__ float g_G[BATCH * C * C];                // G = X X^T  [b][c][d]
__device__ float g_T[BATCH * INNER * C];            // T = Wq @ G [b][o][d]
__device__ float g_attn[BATCH * NH * DH * DH];      // softmax(sim)
__device__ float g_AV[BATCH * INNER * C];           // blockdiag(attn) @ Wv
__device__ float g_Mpart[BATCH * 4 * C * C];        // partial M = Wo @ AV
__device__ float g_M[BATCH * C * C];                // final M

__constant__ int c_ti[6] = {0, 64, 128, 0,  0,   64};
__constant__ int c_tj[6] = {0, 64, 128, 64, 128, 128};

// ---------------- mma helper ----------------
__device__ __forceinline__ void mma16816(float c[4], const uint32_t a[4], const uint32_t b[2]) {
    asm volatile(
        "mma.sync.aligned.m16n8k16.row.col.f32.bf16.bf16.f32 "
        "{%0,%1,%2,%3}, {%4,%5,%6,%7}, {%8,%9}, {%0,%1,%2,%3};\n"
        : "+f"(c[0]), "+f"(c[1]), "+f"(c[2]), "+f"(c[3])
        : "r"(a[0]), "r"(a[1]), "r"(a[2]), "r"(a[3]), "r"(b[0]), "r"(b[1]));
}

__device__ __forceinline__ void split_pack(float x0, float x1, uint32_t& hi, uint32_t& lo) {
    __nv_bfloat16 h0 = __float2bfloat16_rn(x0);
    __nv_bfloat16 h1 = __float2bfloat16_rn(x1);
    __nv_bfloat16 l0 = __float2bfloat16_rn(x0 - __bfloat162float(h0));
    __nv_bfloat16 l1 = __float2bfloat16_rn(x1 - __bfloat162float(h1));
    __nv_bfloat162 hp; hp.x = h0; hp.y = h1;
    __nv_bfloat162 lp; lp.x = l0; lp.y = l1;
    hi = *reinterpret_cast<uint32_t*>(&hp);
    lo = *reinterpret_cast<uint32_t*>(&lp);
}

// ---------------- K1: gram partials, tensor-core, upper-tri tiles ----------------
// grid (6 tiles, GC chunks, BATCH), 256 threads (8 warps: 2m x 4n of a 64x64 tile)
#define GPAD 66   // bf16 row stride
__global__ void __launch_bounds__(256, 2) k_gram(const float* __restrict__ x) {
    int tile  = blockIdx.x;
    int chunk = blockIdx.y;
    int b     = blockIdx.z;
    int i0 = c_ti[tile], j0 = c_tj[tile];
    bool diag = (i0 == j0);
    const float* xb = x + (size_t)b * C * S;

    __shared__ __nv_bfloat16 sA[2 * 64 * GPAD];
    __shared__ __nv_bfloat16 sB[2 * 64 * GPAD];

    int tid  = threadIdx.x;
    int w    = tid >> 5, lane = tid & 31;
    int grp  = lane >> 2, tig = lane & 3;
    int wm   = w & 1, wn = w >> 1;

    float acc[2][2][4] = {};
    int sbeg = chunk * SPB;

    for (int sc = 0; sc < SPB; sc += 64) {
        int sb = sbeg + sc;
        // load + split-convert A rows (i-block); 1024 float4, 4 per thread
        #pragma unroll
        for (int i = 0; i < 4; i++) {
            int idx = tid + i * 256;
            int r = idx >> 4, c4 = (idx & 15) * 4;
            float4 v = *reinterpret_cast<const float4*>(&xb[(size_t)(i0 + r) * S + sb + c4]);
            uint32_t h0, l0, h1, l1;
            split_pack(v.x, v.y, h0, l0);
            split_pack(v.z, v.w, h1, l1);
            int base = r * GPAD + c4;
            *reinterpret_cast<uint32_t*>(&sA[base])              = h0;
            *reinterpret_cast<uint32_t*>(&sA[base + 2])          = h1;
            *reinterpret_cast<uint32_t*>(&sA[64 * GPAD + base])     = l0;
            *reinterpret_cast<uint32_t*>(&sA[64 * GPAD + base + 2]) = l1;
        }
        if (!diag) {
            #pragma unroll
            for (int i = 0; i < 4; i++) {
                int idx = tid + i * 256;
                int r = idx >> 4, c4 = (idx & 15) * 4;
                float4 v = *reinterpret_cast<const float4*>(&xb[(size_t)(j0 + r) * S + sb + c4]);
                uint32_t h0, l0, h1, l1;
                split_pack(v.x, v.y, h0, l0);
                split_pack(v.z, v.w, h1, l1);
                int base = r * GPAD + c4;
                *reinterpret_cast<uint32_t*>(&sB[base])              = h0;
                *reinterpret_cast<uint32_t*>(&sB[base + 2])          = h1;
                *reinterpret_cast<uint32_t*>(&sB[64 * GPAD + base])     = l0;
                *reinterpret_cast<uint32_t*>(&sB[64 * GPAD + base + 2]) = l1;
            }
        }
        __syncthreads();

        const __nv_bfloat16* Bp = diag ? sA : sB;

        #pragma unroll
        for (int ks = 0; ks < 4; ks++) {
            int kb = ks * 16 + tig * 2;
            uint32_t a[2][2][4];  // [split][mf][reg]
            #pragma unroll
            for (int h = 0; h < 2; h++)
                #pragma unroll
                for (int mf = 0; mf < 2; mf++) {
                    int rr = wm * 32 + mf * 16 + grp;
                    int o  = h * 64 * GPAD + rr * GPAD;
                    a[h][mf][0] = *reinterpret_cast<const uint32_t*>(&sA[o + kb]);
                    a[h][mf][1] = *reinterpret_cast<const uint32_t*>(&sA[o + 8 * GPAD + kb]);
                    a[h][mf][2] = *reinterpret_cast<const uint32_t*>(&sA[o + kb + 8]);
                    a[h][mf][3] = *reinterpret_cast<const uint32_t*>(&sA[o + 8 * GPAD + kb + 8]);
                }
            uint32_t bb[2][2][2];  // [split][nf][reg]
            #pragma unroll
            for (int h = 0; h < 2; h++)
                #pragma unroll
                for (int nf = 0; nf < 2; nf++) {
                    int rr = wn * 16 + nf * 8 + grp;
                    int o  = h * 64 * GPAD + rr * GPAD;
                    bb[h][nf][0] = *reinterpret_cast<const uint32_t*>(&Bp[o + kb]);
                    bb[h][nf][1] = *reinterpret_cast<const uint32_t*>(&Bp[o + kb + 8]);
                }
            #pragma unroll
            for (int mf = 0; mf < 2; mf++)
                #pragma unroll
                for (int nf = 0; nf < 2; nf++) {
                    mma16816(acc[mf][nf], a[0][mf], bb[0][nf]);
                    mma16816(acc[mf][nf], a[0][mf], bb[1][nf]);
                    mma16816(acc[mf][nf], a[1][mf], bb[0][nf]);
                }
        }
        __syncthreads();
    }

    float* Gp = g_Gpart + ((size_t)((b * GC + chunk) * 6 + tile)) * 4096;
    #pragma unroll
    for (int mf = 0; mf < 2; mf++)
        #pragma unroll
        for (int nf = 0; nf < 2; nf++) {
            int row = wm * 32 + mf * 16 + grp;
            int col = wn * 16 + nf * 8 + tig * 2;
            *reinterpret_cast<float2*>(&Gp[row * 64 + col])       = make_float2(acc[mf][nf][0], acc[mf][nf][1]);
            *reinterpret_cast<float2*>(&Gp[(row + 8) * 64 + col]) = make_float2(acc[mf][nf][2], acc[mf][nf][3]);
        }
}

// reduce + symmetric fill
__global__ void k_gram_reduce() {
    int tile = blockIdx.x, b = blockIdx.y;
    int i0 = c_ti[tile], j0 = c_tj[tile];
    float* Gb = g_G + (size_t)b * C * C;
    for (int e = threadIdx.x; e < 4096; e += 256) {
        float s = 0.f;
        #pragma unroll
        for (int ch = 0; ch < GC; ch++)
            s += g_Gpart[((size_t)((b * GC + ch) * 6 + tile)) * 4096 + e];
        int m = e >> 6, n = e & 63;
        Gb[(i0 + m) * C + j0 + n] = s;
        Gb[(j0 + n) * C + i0 + m] = s;
    }
}

// ---------------- K2a: T = Wq @ G  (fp32 SIMT, small) ----------------
__global__ void k_qg(const float* __restrict__ wq) {
    int d0 = blockIdx.x * 64;
    int o0 = blockIdx.y * 64;
    int b  = blockIdx.z;

    __shared__ float Ws[64][68];
    __shared__ float Gs[64][68];

    int tid = threadIdx.x;
    int tx = tid & 15, ty = tid >> 4;
    float acc[4][4] = {};
    const float* Gb = g_G + (size_t)b * C * C;

    for (int c0 = 0; c0 < C; c0 += 64) {
        #pragma unroll
        for (int l = 0; l < 16; l++) {
            int idx = tid + l * 256;
            int r = idx >> 6, q = idx & 63;
            Ws[r][q] = wq[(o0 + r) * C + c0 + q];
            Gs[r][q] = Gb[(c0 + r) * C + d0 + q];
        }
        __syncthreads();
        #pragma unroll 16
        for (int c = 0; c < 64; c++) {
            float4 gv = *reinterpret_cast<const float4*>(&Gs[c][tx * 4]);
            float w0 = Ws[ty * 4 + 0][c], w1 = Ws[ty * 4 + 1][c];
            float w2 = Ws[ty * 4 + 2][c], w3 = Ws[ty * 4 + 3][c];
            acc[0][0] += w0 * gv.x; acc[0][1] += w0 * gv.y; acc[0][2] += w0 * gv.z; acc[0][3] += w0 * gv.w;
            acc[1][0] += w1 * gv.x; acc[1][1] += w1 * gv.y; acc[1][2] += w1 * gv.z; acc[1][3] += w1 * gv.w;
            acc[2][0] += w2 * gv.x; acc[2][1] += w2 * gv.y; acc[2][2] += w2 * gv.z; acc[2][3] += w2 * gv.w;
            acc[3][0] += w3 * gv.x; acc[3][1] += w3 * gv.y; acc[3][2] += w3 * gv.z; acc[3][3] += w3 * gv.w;
        }
        __syncthreads();
    }
    float* Tb = g_T + (size_t)b * INNER * C;
    #pragma unroll
    for (int ii = 0; ii < 4; ii++)
        #pragma unroll
        for (int jj = 0; jj < 4; jj++)
            Tb[(o0 + ty * 4 + ii) * C + d0 + tx * 4 + jj] = acc[ii][jj];
}

// ---------------- K2b: sim + softmax ----------------
__global__ void k_sim_softmax(const float* __restrict__ wk) {
    int n = blockIdx.x, b = blockIdx.y;
    __shared__ float buf[2 * 64 * 68];
    float (*Ts)[68] = (float (*)[68])buf;
    float (*Ks)[68] = (float (*)[68])(buf + 64 * 68);

    int tid = threadIdx.x;
    int tx = tid & 15, ty = tid >> 4;
    float acc[4][4] = {};

    const float* Tb = g_T + ((size_t)b * INNER + (size_t)n * DH) * C;
    const float* Kb = wk + (size_t)n * DH * C;

    for (int d0 = 0; d0 < C; d0 += 64) {
        #pragma unroll
        for (int l = 0; l < 16; l++) {
            int idx = tid + l * 256;
            int r = idx >> 6, q = idx & 63;
            Ts[r][q] = Tb[r * C + d0 + q];
            Ks[r][q] = Kb[r * C + d0 + q];
        }
        __syncthreads();
        #pragma unroll 4
        for (int s = 0; s < 64; s += 4) {
            float4 av[4], bv[4];
            #pragma unroll
            for (int k = 0; k < 4; k++) {
                av[k] = *reinterpret_cast<const float4*>(&Ts[ty * 4 + k][s]);
                bv[k] = *reinterpret_cast<const float4*>(&Ks[tx * 4 + k][s]);
            }
            #pragma unroll
            for (int ii = 0; ii < 4; ii++)
                #pragma unroll
                for (int jj = 0; jj < 4; jj++)
                    acc[ii][jj] += av[ii].x * bv[jj].x + av[ii].y * bv[jj].y
                                 + av[ii].z * bv[jj].z + av[ii].w * bv[jj].w;
        }
        __syncthreads();
    }

    float (*sims)[65] = (float (*)[65])buf;
    #pragma unroll
    for (int ii = 0; ii < 4; ii++)
        #pragma unroll
        for (int jj = 0; jj < 4; jj++)
            sims[ty * 4 + ii][tx * 4 + jj] = acc[ii][jj] * ATT_SCALE;
    __syncthreads();

    int w = tid >> 5, lane = tid & 31;
    for (int r = w; r < 64; r += 8) {
        float m = fmaxf(sims[r][lane], sims[r][lane + 32]);
        #pragma unroll
        for (int off = 16; off; off >>= 1)
            m = fmaxf(m, __shfl_xor_sync(0xffffffffu, m, off));
        float e0 = expf(sims[r][lane] - m);
        float e1 = expf(sims[r][lane + 32] - m);
        float sum = e0 + e1;
        #pragma unroll
        for (int off = 16; off; off >>= 1)
            sum += __shfl_xor_sync(0xffffffffu, sum, off);
        float inv = 1.f / sum;
        float* arow = g_attn + (((size_t)(b * NH + n)) * DH + r) * DH;
        arow[lane]      = e0 * inv;
        arow[lane + 32] = e1 * inv;
    }
}

// ---------------- K3a: AV = blockdiag(attn) @ Wv ----------------
__global__ void k_av(const float* __restrict__ wv) {
    int c0 = blockIdx.x * 64;
    int n  = blockIdx.y;
    int b  = blockIdx.z;

    __shared__ float Asm[64][68];
    __shared__ float Vs[64][68];

    int tid = threadIdx.x;
    int tx = tid & 15, ty = tid >> 4;

    #pragma unroll
    for (int l = 0; l < 16; l++) {
        int idx = tid + l * 256;
        int r = idx >> 6, q = idx & 63;
        Asm[r][q] = g_attn[(((size_t)(b * NH + n)) * DH + r) * DH + q];
        Vs[r][q]  = wv[(n * DH + r) * C + c0 + q];
    }
    __syncthreads();

    float acc[4][4] = {};
    #pragma unroll 16
    for (int j = 0; j < 64; j++) {
        float4 vv = *reinterpret_cast<const float4*>(&Vs[j][tx * 4]);
        float a0 = Asm[ty * 4 + 0][j], a1 = Asm[ty * 4 + 1][j];
        float a2 = Asm[ty * 4 + 2][j], a3 = Asm[ty * 4 + 3][j];
        acc[0][0] += a0 * vv.x; acc[0][1] += a0 * vv.y; acc[0][2] += a0 * vv.z; acc[0][3] += a0 * vv.w;
        acc[1][0] += a1 * vv.x; acc[1][1] += a1 * vv.y; acc[1][2] += a1 * vv.z; acc[1][3] += a1 * vv.w;
        acc[2][0] += a2 * vv.x; acc[2][1] += a2 * vv.y; acc[2][2] += a2 * vv.z; acc[2][3] += a2 * vv.w;
        acc[3][0] += a3 * vv.x; acc[3][1] += a3 * vv.y; acc[3][2] += a3 * vv.z; acc[3][3] += a3 * vv.w;
    }
    #pragma unroll
    for (int ii = 0; ii < 4; ii++)
        #pragma unroll
        for (int jj = 0; jj < 4; jj++)
            g_AV[((size_t)b * INNER + n * DH + ty * 4 + ii) * C + c0 + tx * 4 + jj] = acc[ii][jj];
}

// ---------------- K3b: M = Wo @ AV ----------------
__global__ void k_m(const float* __restrict__ wo) {
    int c0 = blockIdx.x * 64;
    int o0 = (blockIdx.y % 3) * 64;
    int kc = blockIdx.y / 3;
    int b  = blockIdx.z;

    __shared__ float Ws[64][68];
    __shared__ float Vs[64][68];

    int tid = threadIdx.x;
    int tx = tid & 15, ty = tid >> 4;
    float acc[4][4] = {};

    for (int kk = 0; kk < 128; kk += 64) {
        int k0 = kc * 128 + kk;
        #pragma unroll
        for (int l = 0; l < 16; l++) {
            int idx = tid + l * 256;
            int r = idx >> 6, q = idx & 63;
            Ws[r][q] = wo[(o0 + r) * INNER + k0 + q];
            Vs[r][q] = g_AV[((size_t)b * INNER + k0 + r) * C + c0 + q];
        }
        __syncthreads();
        #pragma unroll 16
        for (int k = 0; k < 64; k++) {
            float4 vv = *reinterpret_cast<const float4*>(&Vs[k][tx * 4]);
            float w0 = Ws[ty * 4 + 0][k], w1 = Ws[ty * 4 + 1][k];
            float w2 = Ws[ty * 4 + 2][k], w3 = Ws[ty * 4 + 3][k];
            acc[0][0] += w0 * vv.x; acc[0][1] += w0 * vv.y; acc[0][2] += w0 * vv.z; acc[0][3] += w0 * vv.w;
            acc[1][0] += w1 * vv.x; acc[1][1] += w1 * vv.y; acc[1][2] += w1 * vv.z; acc[1][3] += w1 * vv.w;
            acc[2][0] += w2 * vv.x; acc[2][1] += w2 * vv.y; acc[2][2] += w2 * vv.z; acc[2][3] += w2 * vv.w;
            acc[3][0] += w3 * vv.x; acc[3][1] += w3 * vv.y; acc[3][2] += w3 * vv.z; acc[3][3] += w3 * vv.w;
        }
        __syncthreads();
    }
    float* Mp = g_Mpart + ((size_t)(b * 4 + kc)) * C * C;
    #pragma unroll
    for (int ii = 0; ii < 4; ii++)
        #pragma unroll
        for (int jj = 0; jj < 4; jj++)
            Mp[(o0 + ty * 4 + ii) * C + tx * 4 + jj + c0] = acc[ii][jj];
}

__global__ void k_m_reduce() {
    int b = blockIdx.y;
    int e = blockIdx.x * 256 + threadIdx.x;
    if (e < C * C) {
        float s = 0.f;
        #pragma unroll
        for (int kc = 0; kc < 4; kc++)
            s += g_Mpart[((size_t)(b * 4 + kc)) * C * C + e];
        g_M[(size_t)b * C * C + e] = s;
    }
}

// ---------------- K4: out = M @ X + bo, tensor-core ----------------
// grid (S/128, 3, BATCH), 256 thr (8 warps: 2m x 4n), o-tile 64, s-tile 128, k-chunk 32
#define OPAD 34
__global__ void __launch_bounds__(256, 2) k_out(const float* __restrict__ x,
                                                const float* __restrict__ bo,
                                                float* __restrict__ out) {
    int s0 = blockIdx.x * 128;
    int o0 = blockIdx.y * 64;
    int b  = blockIdx.z;

    __shared__ __nv_bfloat16 sM[2 * 64 * OPAD];   // [split][o][k]
    __shared__ __nv_bfloat16 sX[2 * 128 * OPAD];  // [split][s][k] (transposed)

    int tid  = threadIdx.x;
    int w    = tid >> 5, lane = tid & 31;
    int grp  = lane >> 2, tig = lane & 3;
    int wm   = w & 1, wn = w >> 1;

    const float* xb = x + (size_t)b * C * S;
    const float* Mb = g_M + (size_t)b * C * C;

    float acc[2][4][4] = {};

    for (int kc = 0; kc < C; kc += 32) {
        // M block [64 o][32 k]: 512 float4, 2 per thread
        #pragma unroll
        for (int i = 0; i < 2; i++) {
            int idx = tid + i * 256;
            int r = idx >> 3, c4 = (idx & 7) * 4;
            float4 v = *reinterpret_cast<const float4*>(&Mb[(o0 + r) * C + kc + c4]);
            uint32_t h0, l0, h1, l1;
            split_pack(v.x, v.y, h0, l0);
            split_pack(v.z, v.w, h1, l1);
            int base = r * OPAD + c4;
            *reinterpret_cast<uint32_t*>(&sM[base])              = h0;
            *reinterpret_cast<uint32_t*>(&sM[base + 2])          = h1;
            *reinterpret_cast<uint32_t*>(&sM[64 * OPAD + base])     = l0;
            *reinterpret_cast<uint32_t*>(&sM[64 * OPAD + base + 2]) = l1;
        }
        // X block [32 k][128 s] -> transposed sX[s][k], pack (k,k+1) pairs
        #pragma unroll
        for (int u = 0; u < 2; u++) {
            int unit = tid + u * 256;           // 512 units: 16 k-pairs x 32 s4-groups
            int k2 = unit >> 5, s4 = (unit & 31) * 4;
            const float* r0 = &xb[(size_t)(kc + 2 * k2) * S + s0 + s4];
            const float* r1 = r0 + S;
            float4 v0 = *reinterpret_cast<const float4*>(r0);
            float4 v1 = *reinterpret_cast<const float4*>(r1);
            float a0[4] = {v0.x, v0.y, v0.z, v0.w};
            float a1[4] = {v1.x, v1.y, v1.z, v1.w};
            #pragma unroll
            for (int j = 0; j < 4; j++) {
                uint32_t hp, lp;
                split_pack(a0[j], a1[j], hp, lp);
                int base = (s4 + j) * OPAD + 2 * k2;
                *reinterpret_cast<uint32_t*>(&sX[base])             = hp;
                *reinterpret_cast<uint32_t*>(&sX[128 * OPAD + base]) = lp;
            }
        }
        __syncthreads();

        #pragma unroll
        for (int ks = 0; ks < 2; ks++) {
            int kb = ks * 16 + tig * 2;
            uint32_t a[2][2][4];
            #pragma unroll
            for (int h = 0; h < 2; h++)
                #pragma unroll
                for (int mf = 0; mf < 2; mf++) {
                    int rr = wm * 32 + mf * 16 + grp;
                    int o  = h * 64 * OPAD + rr * OPAD;
                    a[h][mf][0] = *reinterpret_cast<const uint32_t*>(&sM[o + kb]);
                    a[h][mf][1] = *reinterpret_cast<const uint32_t*>(&sM[o + 8 * OPAD + kb]);
                    a[h][mf][2] = *reinterpret_cast<const uint32_t*>(&sM[o + kb + 8]);
                    a[h][mf][3] = *reinterpret_cast<const uint32_t*>(&sM[o + 8 * OPAD + kb + 8]);
                }
            uint32_t bb[2][4][2];
            #pragma unroll
            for (int h = 0; h < 2; h++)
                #pragma unroll
                for (int nf = 0; nf < 4; nf++) {
                    int rr = wn * 32 + nf * 8 + grp;
                    int o  = h * 128 * OPAD + rr * OPAD;
                    bb[h][nf][0] = *reinterpret_cast<const uint32_t*>(&sX[o + kb]);
                    bb[h][nf][1] = *reinterpret_cast<const uint32_t*>(&sX[o + kb + 8]);
                }
            #pragma unroll
            for (int mf = 0; mf < 2; mf++)
                #pragma unroll
                for (int nf = 0; nf < 4; nf++) {
                    mma16816(acc[mf][nf], a[0][mf], bb[0][nf]);
                    mma16816(acc[mf][nf], a[0][mf], bb[1][nf]);
                    mma16816(acc[mf][nf], a[1][mf], bb[0][nf]);
                }
        }
        __syncthreads();
    }

    #pragma unroll
    for (int mf = 0; mf < 2; mf++) {
        int row0 = o0 + wm * 32 + mf * 16 + grp;
        float bias0 = bo[row0];
        float bias1 = bo[row0 + 8];
        #pragma unroll
        for (int nf = 0; nf < 4; nf++) {
            int col = s0 + wn * 32 + nf * 8 + tig * 2;
            *reinterpret_cast<float2*>(&out[((size_t)b * C + row0) * S + col]) =
                make_float2(acc[mf][nf][0] + bias0, acc[mf][nf][1] + bias0);
            *reinterpret_cast<float2*>(&out[((size_t)b * C + row0 + 8) * S + col]) =
                make_float2(acc[mf][nf][2] + bias1, acc[mf][nf][3] + bias1);
        }
    }
}

// ---------------- launch ----------------
extern "C" void kernel_launch(void* const* d_in, const int* in_sizes, int n_in,
                              void* d_out, int out_size) {
    const float* x  = (const float*)d_in[0];
    const float* wq = (const float*)d_in[1];
    const float* wk = (const float*)d_in[2];
    const float* wv = (const float*)d_in[3];
    const float* wo = (const float*)d_in[4];
    const float* bo = (const float*)d_in[5];
    float* out = (float*)d_out;

    k_gram<<<dim3(6, GC, BATCH), 256>>>(x);
    k_gram_reduce<<<dim3(6, BATCH), 256>>>();
    k_qg<<<dim3(3, 8, BATCH), 256>>>(wq);
    k_sim_softmax<<<dim3(NH, BATCH), 256>>>(wk);
    k_av<<<dim3(3, NH, BATCH), 256>>>(wv);
    k_m<<<dim3(3, 12, BATCH), 256>>>(wo);
    k_m_reduce<<<dim3(144, BATCH), 256>>>();
    k_out<<<dim3(S / 128, 3, BATCH), 256>>>(x, bo, out);
}

// round 3
// speedup vs baseline: 1.9769x; 1.0671x over previous
#include <cuda_runtime.h>
#include <cuda_bf16.h>
#include <math.h>
#include <stdint.h>

#define BATCH 2
#define C     192
#define S     32768
#define NH    8
#define DH    64
#define INNER 512
#define ATT_SCALE 0.125f
#define GC    32            // gram split-K chunks
#define SPB   (S / GC)      // 1024 spatial per chunk

// ---------------- device scratch ----------------
__device__ float g_Gpart[BATCH * GC * 6 * 64 * 64];
__device__ float g_G[BATCH * C * C];
__device__ float g_T[BATCH * INNER * C];
__device__ float g_attn[BATCH * NH * DH * DH];
__device__ float g_AV[BATCH * INNER * C];
__device__ float g_Mpart[BATCH * 4 * C * C];
__device__ float g_M[BATCH * C * C];

__constant__ int c_ti[6] = {0, 64, 128, 0,  0,   64};
__constant__ int c_tj[6] = {0, 64, 128, 64, 128, 128};

// ---------------- mma helpers ----------------
__device__ __forceinline__ void mma16816(float c[4], const uint32_t a[4], const uint32_t b[2]) {
    asm volatile(
        "mma.sync.aligned.m16n8k16.row.col.f32.bf16.bf16.f32 "
        "{%0,%1,%2,%3}, {%4,%5,%6,%7}, {%8,%9}, {%0,%1,%2,%3};\n"
        : "+f"(c[0]), "+f"(c[1]), "+f"(c[2]), "+f"(c[3])
        : "r"(a[0]), "r"(a[1]), "r"(a[2]), "r"(a[3]), "r"(b[0]), "r"(b[1]));
}

__device__ __forceinline__ void split_pack(float x0, float x1, uint32_t& hi, uint32_t& lo) {
    __nv_bfloat16 h0 = __float2bfloat16_rn(x0);
    __nv_bfloat16 h1 = __float2bfloat16_rn(x1);
    __nv_bfloat16 l0 = __float2bfloat16_rn(x0 - __bfloat162float(h0));
    __nv_bfloat16 l1 = __float2bfloat16_rn(x1 - __bfloat162float(h1));
    __nv_bfloat162 hp; hp.x = h0; hp.y = h1;
    __nv_bfloat162 lp; lp.x = l0; lp.y = l1;
    hi = *reinterpret_cast<uint32_t*>(&hp);
    lo = *reinterpret_cast<uint32_t*>(&lp);
}

// ---------------- K1: gram partials (tensor-core, upper-tri, reg-prefetch pipeline) ----------------
#define GPAD 66
__global__ void __launch_bounds__(256, 2) k_gram(const float* __restrict__ x) {
    int tile  = blockIdx.x;
    int chunk = blockIdx.y;
    int b     = blockIdx.z;
    int i0 = c_ti[tile], j0 = c_tj[tile];
    bool diag = (i0 == j0);
    const float* xb = x + (size_t)b * C * S;

    __shared__ __nv_bfloat16 sA[2 * 64 * GPAD];
    __shared__ __nv_bfloat16 sB[2 * 64 * GPAD];

    int tid  = threadIdx.x;
    int w    = tid >> 5, lane = tid & 31;
    int grp  = lane >> 2, tig = lane & 3;
    int wm   = w & 1, wn = w >> 1;

    float acc[2][2][4] = {};
    int sbeg = chunk * SPB;
    int lr = tid >> 4, lc = (tid & 15) * 4;   // load coords: row lr(+16..), col lc

    float4 pa[4], pb[4];
    #pragma unroll
    for (int i = 0; i < 4; i++)
        pa[i] = *reinterpret_cast<const float4*>(&xb[(size_t)(i0 + lr + i * 16) * S + sbeg + lc]);
    if (!diag)
        #pragma unroll
        for (int i = 0; i < 4; i++)
            pb[i] = *reinterpret_cast<const float4*>(&xb[(size_t)(j0 + lr + i * 16) * S + sbeg + lc]);

    for (int sc = 0; sc < SPB; sc += 64) {
        // convert + STS current chunk from registers
        #pragma unroll
        for (int i = 0; i < 4; i++) {
            uint32_t h0, l0, h1, l1;
            split_pack(pa[i].x, pa[i].y, h0, l0);
            split_pack(pa[i].z, pa[i].w, h1, l1);
            int base = (lr + i * 16) * GPAD + lc;
            *reinterpret_cast<uint32_t*>(&sA[base])                 = h0;
            *reinterpret_cast<uint32_t*>(&sA[base + 2])             = h1;
            *reinterpret_cast<uint32_t*>(&sA[64 * GPAD + base])     = l0;
            *reinterpret_cast<uint32_t*>(&sA[64 * GPAD + base + 2]) = l1;
        }
        if (!diag) {
            #pragma unroll
            for (int i = 0; i < 4; i++) {
                uint32_t h0, l0, h1, l1;
                split_pack(pb[i].x, pb[i].y, h0, l0);
                split_pack(pb[i].z, pb[i].w, h1, l1);
                int base = (lr + i * 16) * GPAD + lc;
                *reinterpret_cast<uint32_t*>(&sB[base])                 = h0;
                *reinterpret_cast<uint32_t*>(&sB[base + 2])             = h1;
                *reinterpret_cast<uint32_t*>(&sB[64 * GPAD + base])     = l0;
                *reinterpret_cast<uint32_t*>(&sB[64 * GPAD + base + 2]) = l1;
            }
        }
        __syncthreads();

        // prefetch next chunk while mma runs
        if (sc + 64 < SPB) {
            int sb = sbeg + sc + 64;
            #pragma unroll
            for (int i = 0; i < 4; i++)
                pa[i] = *reinterpret_cast<const float4*>(&xb[(size_t)(i0 + lr + i * 16) * S + sb + lc]);
            if (!diag)
                #pragma unroll
                for (int i = 0; i < 4; i++)
                    pb[i] = *reinterpret_cast<const float4*>(&xb[(size_t)(j0 + lr + i * 16) * S + sb + lc]);
        }

        const __nv_bfloat16* Bp = diag ? sA : sB;
        #pragma unroll
        for (int ks = 0; ks < 4; ks++) {
            int kb = ks * 16 + tig * 2;
            uint32_t a[2][2][4];
            #pragma unroll
            for (int h = 0; h < 2; h++)
                #pragma unroll
                for (int mf = 0; mf < 2; mf++) {
                    int rr = wm * 32 + mf * 16 + grp;
                    int o  = h * 64 * GPAD + rr * GPAD;
                    a[h][mf][0] = *reinterpret_cast<const uint32_t*>(&sA[o + kb]);
                    a[h][mf][1] = *reinterpret_cast<const uint32_t*>(&sA[o + 8 * GPAD + kb]);
                    a[h][mf][2] = *reinterpret_cast<const uint32_t*>(&sA[o + kb + 8]);
                    a[h][mf][3] = *reinterpret_cast<const uint32_t*>(&sA[o + 8 * GPAD + kb + 8]);
                }
            uint32_t bb[2][2][2];
            #pragma unroll
            for (int h = 0; h < 2; h++)
                #pragma unroll
                for (int nf = 0; nf < 2; nf++) {
                    int rr = wn * 16 + nf * 8 + grp;
                    int o  = h * 64 * GPAD + rr * GPAD;
                    bb[h][nf][0] = *reinterpret_cast<const uint32_t*>(&Bp[o + kb]);
                    bb[h][nf][1] = *reinterpret_cast<const uint32_t*>(&Bp[o + kb + 8]);
                }
            #pragma unroll
            for (int mf = 0; mf < 2; mf++)
                #pragma unroll
                for (int nf = 0; nf < 2; nf++) {
                    mma16816(acc[mf][nf], a[0][mf], bb[0][nf]);
                    mma16816(acc[mf][nf], a[0][mf], bb[1][nf]);
                    mma16816(acc[mf][nf], a[1][mf], bb[0][nf]);
                }
        }
        __syncthreads();
    }

    float* Gp = g_Gpart + ((size_t)((b * GC + chunk) * 6 + tile)) * 4096;
    #pragma unroll
    for (int mf = 0; mf < 2; mf++)
        #pragma unroll
        for (int nf = 0; nf < 2; nf++) {
            int row = wm * 32 + mf * 16 + grp;
            int col = wn * 16 + nf * 8 + tig * 2;
            *reinterpret_cast<float2*>(&Gp[row * 64 + col])       = make_float2(acc[mf][nf][0], acc[mf][nf][1]);
            *reinterpret_cast<float2*>(&Gp[(row + 8) * 64 + col]) = make_float2(acc[mf][nf][2], acc[mf][nf][3]);
        }
}

__global__ void k_gram_reduce() {
    int tile = blockIdx.x, b = blockIdx.y;
    int i0 = c_ti[tile], j0 = c_tj[tile];
    float* Gb = g_G + (size_t)b * C * C;
    for (int e = threadIdx.x; e < 4096; e += 256) {
        float s = 0.f;
        #pragma unroll
        for (int ch = 0; ch < GC; ch++)
            s += g_Gpart[((size_t)((b * GC + ch) * 6 + tile)) * 4096 + e];
        int m = e >> 6, n = e & 63;
        Gb[(i0 + m) * C + j0 + n] = s;
        Gb[(j0 + n) * C + i0 + m] = s;
    }
}

// ---------------- K2a: T = Wq @ G ----------------
__global__ void k_qg(const float* __restrict__ wq) {
    int d0 = blockIdx.x * 64;
    int o0 = blockIdx.y * 64;
    int b  = blockIdx.z;

    __shared__ float Ws[64][68];
    __shared__ float Gs[64][68];

    int tid = threadIdx.x;
    int tx = tid & 15, ty = tid >> 4;
    float acc[4][4] = {};
    const float* Gb = g_G + (size_t)b * C * C;

    for (int c0 = 0; c0 < C; c0 += 64) {
        #pragma unroll
        for (int l = 0; l < 16; l++) {
            int idx = tid + l * 256;
            int r = idx >> 6, q = idx & 63;
            Ws[r][q] = wq[(o0 + r) * C + c0 + q];
            Gs[r][q] = Gb[(c0 + r) * C + d0 + q];
        }
        __syncthreads();
        #pragma unroll 16
        for (int c = 0; c < 64; c++) {
            float4 gv = *reinterpret_cast<const float4*>(&Gs[c][tx * 4]);
            float w0 = Ws[ty * 4 + 0][c], w1 = Ws[ty * 4 + 1][c];
            float w2 = Ws[ty * 4 + 2][c], w3 = Ws[ty * 4 + 3][c];
            acc[0][0] += w0 * gv.x; acc[0][1] += w0 * gv.y; acc[0][2] += w0 * gv.z; acc[0][3] += w0 * gv.w;
            acc[1][0] += w1 * gv.x; acc[1][1] += w1 * gv.y; acc[1][2] += w1 * gv.z; acc[1][3] += w1 * gv.w;
            acc[2][0] += w2 * gv.x; acc[2][1] += w2 * gv.y; acc[2][2] += w2 * gv.z; acc[2][3] += w2 * gv.w;
            acc[3][0] += w3 * gv.x; acc[3][1] += w3 * gv.y; acc[3][2] += w3 * gv.z; acc[3][3] += w3 * gv.w;
        }
        __syncthreads();
    }
    float* Tb = g_T + (size_t)b * INNER * C;
    #pragma unroll
    for (int ii = 0; ii < 4; ii++)
        #pragma unroll
        for (int jj = 0; jj < 4; jj++)
            Tb[(o0 + ty * 4 + ii) * C + d0 + tx * 4 + jj] = acc[ii][jj];
}

// ---------------- K2b: sim + softmax (conflict-free column mapping) ----------------
__global__ void k_sim_softmax(const float* __restrict__ wk) {
    int n = blockIdx.x, b = blockIdx.y;
    __shared__ float buf[2 * 64 * 68];
    float (*Ts)[68] = (float (*)[68])buf;
    float (*Ks)[68] = (float (*)[68])(buf + 64 * 68);

    int tid = threadIdx.x;
    int tx = tid & 15, ty = tid >> 4;
    float acc[4][4] = {};

    const float* Tb = g_T + ((size_t)b * INNER + (size_t)n * DH) * C;
    const float* Kb = wk + (size_t)n * DH * C;

    for (int d0 = 0; d0 < C; d0 += 64) {
        #pragma unroll
        for (int l = 0; l < 16; l++) {
            int idx = tid + l * 256;
            int r = idx >> 6, q = idx & 63;
            Ts[r][q] = Tb[r * C + d0 + q];
            Ks[r][q] = Kb[r * C + d0 + q];
        }
        __syncthreads();
        // rows: ty*4+ii (broadcast within warp); cols: tx+16*jj (lane stride 17 16B-units -> conflict-free)
        #pragma unroll 4
        for (int s = 0; s < 64; s += 4) {
            float4 av[4], bv[4];
            #pragma unroll
            for (int k = 0; k < 4; k++) {
                av[k] = *reinterpret_cast<const float4*>(&Ts[ty * 4 + k][s]);
                bv[k] = *reinterpret_cast<const float4*>(&Ks[tx + 16 * k][s]);
            }
            #pragma unroll
            for (int ii = 0; ii < 4; ii++)
                #pragma unroll
                for (int jj = 0; jj < 4; jj++)
                    acc[ii][jj] += av[ii].x * bv[jj].x + av[ii].y * bv[jj].y
                                 + av[ii].z * bv[jj].z + av[ii].w * bv[jj].w;
        }
        __syncthreads();
    }

    float (*sims)[65] = (float (*)[65])buf;
    #pragma unroll
    for (int ii = 0; ii < 4; ii++)
        #pragma unroll
        for (int jj = 0; jj < 4; jj++)
            sims[ty * 4 + ii][tx + 16 * jj] = acc[ii][jj] * ATT_SCALE;
    __syncthreads();

    int w = tid >> 5, lane = tid & 31;
    for (int r = w; r < 64; r += 8) {
        float m = fmaxf(sims[r][lane], sims[r][lane + 32]);
        #pragma unroll
        for (int off = 16; off; off >>= 1)
            m = fmaxf(m, __shfl_xor_sync(0xffffffffu, m, off));
        float e0 = __expf(sims[r][lane] - m);
        float e1 = __expf(sims[r][lane + 32] - m);
        float sum = e0 + e1;
        #pragma unroll
        for (int off = 16; off; off >>= 1)
            sum += __shfl_xor_sync(0xffffffffu, sum, off);
        float inv = 1.f / sum;
        float* arow = g_attn + (((size_t)(b * NH + n)) * DH + r) * DH;
        arow[lane]      = e0 * inv;
        arow[lane + 32] = e1 * inv;
    }
}

// ---------------- K3a: AV = blockdiag(attn) @ Wv ----------------
__global__ void k_av(const float* __restrict__ wv) {
    int c0 = blockIdx.x * 64;
    int n  = blockIdx.y;
    int b  = blockIdx.z;

    __shared__ float Asm[64][68];
    __shared__ float Vs[64][68];

    int tid = threadIdx.x;
    int tx = tid & 15, ty = tid >> 4;

    #pragma unroll
    for (int l = 0; l < 16; l++) {
        int idx = tid + l * 256;
        int r = idx >> 6, q = idx & 63;
        Asm[r][q] = g_attn[(((size_t)(b * NH + n)) * DH + r) * DH + q];
        Vs[r][q]  = wv[(n * DH + r) * C + c0 + q];
    }
    __syncthreads();

    float acc[4][4] = {};
    #pragma unroll 16
    for (int j = 0; j < 64; j++) {
        float4 vv = *reinterpret_cast<const float4*>(&Vs[j][tx * 4]);
        float a0 = Asm[ty * 4 + 0][j], a1 = Asm[ty * 4 + 1][j];
        float a2 = Asm[ty * 4 + 2][j], a3 = Asm[ty * 4 + 3][j];
        acc[0][0] += a0 * vv.x; acc[0][1] += a0 * vv.y; acc[0][2] += a0 * vv.z; acc[0][3] += a0 * vv.w;
        acc[1][0] += a1 * vv.x; acc[1][1] += a1 * vv.y; acc[1][2] += a1 * vv.z; acc[1][3] += a1 * vv.w;
        acc[2][0] += a2 * vv.x; acc[2][1] += a2 * vv.y; acc[2][2] += a2 * vv.z; acc[2][3] += a2 * vv.w;
        acc[3][0] += a3 * vv.x; acc[3][1] += a3 * vv.y; acc[3][2] += a3 * vv.z; acc[3][3] += a3 * vv.w;
    }
    #pragma unroll
    for (int ii = 0; ii < 4; ii++)
        #pragma unroll
        for (int jj = 0; jj < 4; jj++)
            g_AV[((size_t)b * INNER + n * DH + ty * 4 + ii) * C + c0 + tx * 4 + jj] = acc[ii][jj];
}

// ---------------- K3b: M = Wo @ AV ----------------
__global__ void k_m(const float* __restrict__ wo) {
    int c0 = blockIdx.x * 64;
    int o0 = (blockIdx.y % 3) * 64;
    int kc = blockIdx.y / 3;
    int b  = blockIdx.z;

    __shared__ float Ws[64][68];
    __shared__ float Vs[64][68];

    int tid = threadIdx.x;
    int tx = tid & 15, ty = tid >> 4;
    float acc[4][4] = {};

    for (int kk = 0; kk < 128; kk += 64) {
        int k0 = kc * 128 + kk;
        #pragma unroll
        for (int l = 0; l < 16; l++) {
            int idx = tid + l * 256;
            int r = idx >> 6, q = idx & 63;
            Ws[r][q] = wo[(o0 + r) * INNER + k0 + q];
            Vs[r][q] = g_AV[((size_t)b * INNER + k0 + r) * C + c0 + q];
        }
        __syncthreads();
        #pragma unroll 16
        for (int k = 0; k < 64; k++) {
            float4 vv = *reinterpret_cast<const float4*>(&Vs[k][tx * 4]);
            float w0 = Ws[ty * 4 + 0][k], w1 = Ws[ty * 4 + 1][k];
            float w2 = Ws[ty * 4 + 2][k], w3 = Ws[ty * 4 + 3][k];
            acc[0][0] += w0 * vv.x; acc[0][1] += w0 * vv.y; acc[0][2] += w0 * vv.z; acc[0][3] += w0 * vv.w;
            acc[1][0] += w1 * vv.x; acc[1][1] += w1 * vv.y; acc[1][2] += w1 * vv.z; acc[1][3] += w1 * vv.w;
            acc[2][0] += w2 * vv.x; acc[2][1] += w2 * vv.y; acc[2][2] += w2 * vv.z; acc[2][3] += w2 * vv.w;
            acc[3][0] += w3 * vv.x; acc[3][1] += w3 * vv.y; acc[3][2] += w3 * vv.z; acc[3][3] += w3 * vv.w;
        }
        __syncthreads();
    }
    float* Mp = g_Mpart + ((size_t)(b * 4 + kc)) * C * C;
    #pragma unroll
    for (int ii = 0; ii < 4; ii++)
        #pragma unroll
        for (int jj = 0; jj < 4; jj++)
            Mp[(o0 + ty * 4 + ii) * C + tx * 4 + jj + c0] = acc[ii][jj];
}

__global__ void k_m_reduce() {
    int b = blockIdx.y;
    int e = blockIdx.x * 256 + threadIdx.x;
    if (e < C * C) {
        float s = 0.f;
        #pragma unroll
        for (int kc = 0; kc < 4; kc++)
            s += g_Mpart[((size_t)(b * 4 + kc)) * C * C + e];
        g_M[(size_t)b * C * C + e] = s;
    }
}

// ---------------- K4: out = M @ X + bo (tensor-core, reg-prefetch pipeline) ----------------
#define OPAD 34
__global__ void __launch_bounds__(256, 2) k_out(const float* __restrict__ x,
                                                const float* __restrict__ bo,
                                                float* __restrict__ out) {
    int s0 = blockIdx.x * 128;
    int o0 = blockIdx.y * 64;
    int b  = blockIdx.z;

    __shared__ __nv_bfloat16 sM[2 * 64 * OPAD];
    __shared__ __nv_bfloat16 sX[2 * 128 * OPAD];

    int tid  = threadIdx.x;
    int w    = tid >> 5, lane = tid & 31;
    int grp  = lane >> 2, tig = lane & 3;
    int wm   = w & 1, wn = w >> 1;

    const float* xb = x + (size_t)b * C * S;
    const float* Mb = g_M + (size_t)b * C * C;

    float acc[2][4][4] = {};

    // load coords
    int mr = tid >> 3, mc = (tid & 7) * 4;               // M: rows mr, mr+32 ; cols mc
    int xk2 = tid >> 5, xs4 = (tid & 31) * 4;            // X: k-pairs xk2, xk2+8 ; s-cols xs4

    float4 pm[2], px0[2], px1[2];
    {
        pm[0] = *reinterpret_cast<const float4*>(&Mb[(o0 + mr) * C + mc]);
        pm[1] = *reinterpret_cast<const float4*>(&Mb[(o0 + mr + 32) * C + mc]);
        #pragma unroll
        for (int u = 0; u < 2; u++) {
            const float* r0 = &xb[(size_t)(2 * (xk2 + u * 8)) * S + s0 + xs4];
            px0[u] = *reinterpret_cast<const float4*>(r0);
            px1[u] = *reinterpret_cast<const float4*>(r0 + S);
        }
    }

    for (int kc = 0; kc < C; kc += 32) {
        // convert + STS from registers
        #pragma unroll
        for (int i = 0; i < 2; i++) {
            uint32_t h0, l0, h1, l1;
            split_pack(pm[i].x, pm[i].y, h0, l0);
            split_pack(pm[i].z, pm[i].w, h1, l1);
            int base = (mr + i * 32) * OPAD + mc;
            *reinterpret_cast<uint32_t*>(&sM[base])                 = h0;
            *reinterpret_cast<uint32_t*>(&sM[base + 2])             = h1;
            *reinterpret_cast<uint32_t*>(&sM[64 * OPAD + base])     = l0;
            *reinterpret_cast<uint32_t*>(&sM[64 * OPAD + base + 2]) = l1;
        }
        #pragma unroll
        for (int u = 0; u < 2; u++) {
            float a0[4] = {px0[u].x, px0[u].y, px0[u].z, px0[u].w};
            float a1[4] = {px1[u].x, px1[u].y, px1[u].z, px1[u].w};
            #pragma unroll
            for (int j = 0; j < 4; j++) {
                uint32_t hp, lp;
                split_pack(a0[j], a1[j], hp, lp);
                int base = (xs4 + j) * OPAD + 2 * (xk2 + u * 8);
                *reinterpret_cast<uint32_t*>(&sX[base])              = hp;
                *reinterpret_cast<uint32_t*>(&sX[128 * OPAD + base]) = lp;
            }
        }
        __syncthreads();

        // prefetch next k-chunk
        if (kc + 32 < C) {
            pm[0] = *reinterpret_cast<const float4*>(&Mb[(o0 + mr) * C + kc + 32 + mc]);
            pm[1] = *reinterpret_cast<const float4*>(&Mb[(o0 + mr + 32) * C + kc + 32 + mc]);
            #pragma unroll
            for (int u = 0; u < 2; u++) {
                const float* r0 = &xb[(size_t)(kc + 32 + 2 * (xk2 + u * 8)) * S + s0 + xs4];
                px0[u] = *reinterpret_cast<const float4*>(r0);
                px1[u] = *reinterpret_cast<const float4*>(r0 + S);
            }
        }

        #pragma unroll
        for (int ks = 0; ks < 2; ks++) {
            int kb = ks * 16 + tig * 2;
            uint32_t a[2][2][4];
            #pragma unroll
            for (int h = 0; h < 2; h++)
                #pragma unroll
                for (int mf = 0; mf < 2; mf++) {
                    int rr = wm * 32 + mf * 16 + grp;
                    int o  = h * 64 * OPAD + rr * OPAD;
                    a[h][mf][0] = *reinterpret_cast<const uint32_t*>(&sM[o + kb]);
                    a[h][mf][1] = *reinterpret_cast<const uint32_t*>(&sM[o + 8 * OPAD + kb]);
                    a[h][mf][2] = *reinterpret_cast<const uint32_t*>(&sM[o + kb + 8]);
                    a[h][mf][3] = *reinterpret_cast<const uint32_t*>(&sM[o + 8 * OPAD + kb + 8]);
                }
            uint32_t bb[2][4][2];
            #pragma unroll
            for (int h = 0; h < 2; h++)
                #pragma unroll
                for (int nf = 0; nf < 4; nf++) {
                    int rr = wn * 32 + nf * 8 + grp;
                    int o  = h * 128 * OPAD + rr * OPAD;
                    bb[h][nf][0] = *reinterpret_cast<const uint32_t*>(&sX[o + kb]);
                    bb[h][nf][1] = *reinterpret_cast<const uint32_t*>(&sX[o + kb + 8]);
                }
            #pragma unroll
            for (int mf = 0; mf < 2; mf++)
                #pragma unroll
                for (int nf = 0; nf < 4; nf++) {
                    mma16816(acc[mf][nf], a[0][mf], bb[0][nf]);
                    mma16816(acc[mf][nf], a[0][mf], bb[1][nf]);
                    mma16816(acc[mf][nf], a[1][mf], bb[0][nf]);
                }
        }
        __syncthreads();
    }

    #pragma unroll
    for (int mf = 0; mf < 2; mf++) {
        int row0 = o0 + wm * 32 + mf * 16 + grp;
        float bias0 = bo[row0];
        float bias1 = bo[row0 + 8];
        #pragma unroll
        for (int nf = 0; nf < 4; nf++) {
            int col = s0 + wn * 32 + nf * 8 + tig * 2;
            *reinterpret_cast<float2*>(&out[((size_t)b * C + row0) * S + col]) =
                make_float2(acc[mf][nf][0] + bias0, acc[mf][nf][1] + bias0);
            *reinterpret_cast<float2*>(&out[((size_t)b * C + row0 + 8) * S + col]) =
                make_float2(acc[mf][nf][2] + bias1, acc[mf][nf][3] + bias1);
        }
    }
}

// ---------------- launch ----------------
extern "C" void kernel_launch(void* const* d_in, const int* in_sizes, int n_in,
                              void* d_out, int out_size) {
    const float* x  = (const float*)d_in[0];
    const float* wq = (const float*)d_in[1];
    const float* wk = (const float*)d_in[2];
    const float* wv = (const float*)d_in[3];
    const float* wo = (const float*)d_in[4];
    const float* bo = (const float*)d_in[5];
    float* out = (float*)d_out;

    k_gram<<<dim3(6, GC, BATCH), 256>>>(x);
    k_gram_reduce<<<dim3(6, BATCH), 256>>>();
    k_qg<<<dim3(3, 8, BATCH), 256>>>(wq);
    k_sim_softmax<<<dim3(NH, BATCH), 256>>>(wk);
    k_av<<<dim3(3, NH, BATCH), 256>>>(wv);
    k_m<<<dim3(3, 12, BATCH), 256>>>(wo);
    k_m_reduce<<<dim3(144, BATCH), 256>>>();
    k_out<<<dim3(S / 128, 3, BATCH), 256>>>(x, bo, out);
}

// round 4
// speedup vs baseline: 2.4735x; 1.2512x over previous
#include <cuda_runtime.h>
#include <cuda_bf16.h>
#include <math.h>
#include <stdint.h>

#define BATCH 2
#define C     192
#define S     32768
#define NH    8
#define DH    64
#define INNER 512
#define ATT_SCALE 0.125f
#define GC    32
#define SPB   (S / GC)      // 1024

// ---------------- device scratch ----------------
__device__ float g_Gpart[BATCH * GC * 6 * 64 * 64];
__device__ float g_G[BATCH * C * C];
__device__ float g_T[BATCH * INNER * C];
__device__ float g_attn[BATCH * NH * DH * DH];
__device__ float g_AV[BATCH * INNER * C];
__device__ float g_Mpart[BATCH * 4 * C * C];
__device__ float g_M[BATCH * C * C];

__constant__ int c_ti[6] = {0, 64, 128, 0,  0,   64};
__constant__ int c_tj[6] = {0, 64, 128, 64, 128, 128};

// ---------------- helpers ----------------
__device__ __forceinline__ uint32_t s2u(const void* p) {
    return (uint32_t)__cvta_generic_to_shared(p);
}

#define LDSM4(R0,R1,R2,R3,ADDR) \
    asm volatile("ldmatrix.sync.aligned.m8n8.x4.shared.b16 {%0,%1,%2,%3}, [%4];" \
        : "=r"(R0),"=r"(R1),"=r"(R2),"=r"(R3) : "r"(ADDR))

#define LDSM4T(R0,R1,R2,R3,ADDR) \
    asm volatile("ldmatrix.sync.aligned.m8n8.x4.trans.shared.b16 {%0,%1,%2,%3}, [%4];" \
        : "=r"(R0),"=r"(R1),"=r"(R2),"=r"(R3) : "r"(ADDR))

__device__ __forceinline__ void mma2(float c[4], uint32_t a0, uint32_t a1, uint32_t a2, uint32_t a3,
                                     uint32_t b0, uint32_t b1) {
    asm volatile(
        "mma.sync.aligned.m16n8k16.row.col.f32.bf16.bf16.f32 "
        "{%0,%1,%2,%3}, {%4,%5,%6,%7}, {%8,%9}, {%0,%1,%2,%3};\n"
        : "+f"(c[0]), "+f"(c[1]), "+f"(c[2]), "+f"(c[3])
        : "r"(a0), "r"(a1), "r"(a2), "r"(a3), "r"(b0), "r"(b1));
}

__device__ __forceinline__ void split_pack(float x0, float x1, uint32_t& hi, uint32_t& lo) {
    __nv_bfloat16 h0 = __float2bfloat16_rn(x0);
    __nv_bfloat16 h1 = __float2bfloat16_rn(x1);
    __nv_bfloat16 l0 = __float2bfloat16_rn(x0 - __bfloat162float(h0));
    __nv_bfloat16 l1 = __float2bfloat16_rn(x1 - __bfloat162float(h1));
    __nv_bfloat162 hp; hp.x = h0; hp.y = h1;
    __nv_bfloat162 lp; lp.x = l0; lp.y = l1;
    hi = *reinterpret_cast<uint32_t*>(&hp);
    lo = *reinterpret_cast<uint32_t*>(&lp);
}

// ============ K1: gram partials (ldmatrix + 2-stage double buffer) ============
// smem per stage: A [2 splits][64][GPAD], B same. GPAD*2B = 144B = 9 x 16B (odd -> conflict-free LDSM)
#define GPAD 72
#define G_SPLIT_OFF (64 * GPAD)          // elems
#define G_A_BYTES   (2 * 64 * GPAD * 2)  // 18432
#define G_STAGE     (2 * G_A_BYTES)      // 36864 (A + B)
#define G_SMEM      (2 * G_STAGE)        // 73728

__global__ void __launch_bounds__(256, 2) k_gram(const float* __restrict__ x) {
    extern __shared__ char dyn[];
    int tile  = blockIdx.x;
    int chunk = blockIdx.y;
    int b     = blockIdx.z;
    int i0 = c_ti[tile], j0 = c_tj[tile];
    bool diag = (i0 == j0);
    const float* xb = x + (size_t)b * C * S;

    int tid  = threadIdx.x;
    int w    = tid >> 5, lane = tid & 31;
    int grp  = lane >> 2, tig = lane & 3;
    int wm   = w & 1, wn = w >> 1;
    int rsel = lane & 15, csel = (lane >> 4) << 3;  // ldmatrix lane addressing

    float acc[2][2][4] = {};
    int sbeg = chunk * SPB;
    int lr = tid >> 4, lc = (tid & 15) * 4;

    float4 pa[4], pb[4];
    #pragma unroll
    for (int i = 0; i < 4; i++)
        pa[i] = *reinterpret_cast<const float4*>(&xb[(size_t)(i0 + lr + i * 16) * S + sbeg + lc]);
    if (!diag)
        #pragma unroll
        for (int i = 0; i < 4; i++)
            pb[i] = *reinterpret_cast<const float4*>(&xb[(size_t)(j0 + lr + i * 16) * S + sbeg + lc]);

    // convert chunk 0 into stage 0
    {
        __nv_bfloat16* sA = (__nv_bfloat16*)(dyn);
        __nv_bfloat16* sB = (__nv_bfloat16*)(dyn + G_A_BYTES);
        #pragma unroll
        for (int i = 0; i < 4; i++) {
            uint32_t h0, l0, h1, l1;
            split_pack(pa[i].x, pa[i].y, h0, l0);
            split_pack(pa[i].z, pa[i].w, h1, l1);
            int base = (lr + i * 16) * GPAD + lc;
            *reinterpret_cast<uint2*>(&sA[base])               = make_uint2(h0, h1);
            *reinterpret_cast<uint2*>(&sA[G_SPLIT_OFF + base]) = make_uint2(l0, l1);
        }
        if (!diag)
            #pragma unroll
            for (int i = 0; i < 4; i++) {
                uint32_t h0, l0, h1, l1;
                split_pack(pb[i].x, pb[i].y, h0, l0);
                split_pack(pb[i].z, pb[i].w, h1, l1);
                int base = (lr + i * 16) * GPAD + lc;
                *reinterpret_cast<uint2*>(&sB[base])               = make_uint2(h0, h1);
                *reinterpret_cast<uint2*>(&sB[G_SPLIT_OFF + base]) = make_uint2(l0, l1);
            }
    }
    __syncthreads();

    for (int it = 0; it < SPB / 64; it++) {
        int cur = it & 1;
        bool more = (it + 1 < SPB / 64);

        // prefetch next chunk into registers
        if (more) {
            int sb = sbeg + (it + 1) * 64;
            #pragma unroll
            for (int i = 0; i < 4; i++)
                pa[i] = *reinterpret_cast<const float4*>(&xb[(size_t)(i0 + lr + i * 16) * S + sb + lc]);
            if (!diag)
                #pragma unroll
                for (int i = 0; i < 4; i++)
                    pb[i] = *reinterpret_cast<const float4*>(&xb[(size_t)(j0 + lr + i * 16) * S + sb + lc]);
        }

        // mma on current stage
        uint32_t sAu = s2u(dyn + cur * G_STAGE);
        uint32_t sBu = diag ? sAu : (sAu + G_A_BYTES);
        #pragma unroll
        for (int ks = 0; ks < 4; ks++) {
            int kb = ks * 16;
            uint32_t a[2][2][4];
            #pragma unroll
            for (int h = 0; h < 2; h++)
                #pragma unroll
                for (int mf = 0; mf < 2; mf++) {
                    uint32_t addr = sAu + 2 * (h * G_SPLIT_OFF + (wm * 32 + mf * 16 + rsel) * GPAD + kb + csel);
                    LDSM4(a[h][mf][0], a[h][mf][1], a[h][mf][2], a[h][mf][3], addr);
                }
            uint32_t bm[2][4];
            #pragma unroll
            for (int h = 0; h < 2; h++) {
                uint32_t addr = sBu + 2 * (h * G_SPLIT_OFF + (wn * 16 + rsel) * GPAD + kb + csel);
                LDSM4(bm[h][0], bm[h][1], bm[h][2], bm[h][3], addr);
            }
            #pragma unroll
            for (int mf = 0; mf < 2; mf++)
                #pragma unroll
                for (int nf = 0; nf < 2; nf++) {
                    mma2(acc[mf][nf], a[0][mf][0], a[0][mf][1], a[0][mf][2], a[0][mf][3], bm[0][nf], bm[0][nf + 2]);
                    mma2(acc[mf][nf], a[0][mf][0], a[0][mf][1], a[0][mf][2], a[0][mf][3], bm[1][nf], bm[1][nf + 2]);
                    mma2(acc[mf][nf], a[1][mf][0], a[1][mf][1], a[1][mf][2], a[1][mf][3], bm[0][nf], bm[0][nf + 2]);
                }
        }

        // convert next chunk into other stage
        if (more) {
            __nv_bfloat16* sA = (__nv_bfloat16*)(dyn + (cur ^ 1) * G_STAGE);
            __nv_bfloat16* sB = (__nv_bfloat16*)(dyn + (cur ^ 1) * G_STAGE + G_A_BYTES);
            #pragma unroll
            for (int i = 0; i < 4; i++) {
                uint32_t h0, l0, h1, l1;
                split_pack(pa[i].x, pa[i].y, h0, l0);
                split_pack(pa[i].z, pa[i].w, h1, l1);
                int base = (lr + i * 16) * GPAD + lc;
                *reinterpret_cast<uint2*>(&sA[base])               = make_uint2(h0, h1);
                *reinterpret_cast<uint2*>(&sA[G_SPLIT_OFF + base]) = make_uint2(l0, l1);
            }
            if (!diag)
                #pragma unroll
                for (int i = 0; i < 4; i++) {
                    uint32_t h0, l0, h1, l1;
                    split_pack(pb[i].x, pb[i].y, h0, l0);
                    split_pack(pb[i].z, pb[i].w, h1, l1);
                    int base = (lr + i * 16) * GPAD + lc;
                    *reinterpret_cast<uint2*>(&sB[base])               = make_uint2(h0, h1);
                    *reinterpret_cast<uint2*>(&sB[G_SPLIT_OFF + base]) = make_uint2(l0, l1);
                }
        }
        __syncthreads();
    }

    float* Gp = g_Gpart + ((size_t)((b * GC + chunk) * 6 + tile)) * 4096;
    #pragma unroll
    for (int mf = 0; mf < 2; mf++)
        #pragma unroll
        for (int nf = 0; nf < 2; nf++) {
            int row = wm * 32 + mf * 16 + grp;
            int col = wn * 16 + nf * 8 + tig * 2;
            *reinterpret_cast<float2*>(&Gp[row * 64 + col])       = make_float2(acc[mf][nf][0], acc[mf][nf][1]);
            *reinterpret_cast<float2*>(&Gp[(row + 8) * 64 + col]) = make_float2(acc[mf][nf][2], acc[mf][nf][3]);
        }
}

__global__ void k_gram_reduce() {
    int tile = blockIdx.x, b = blockIdx.y;
    int i0 = c_ti[tile], j0 = c_tj[tile];
    float* Gb = g_G + (size_t)b * C * C;
    for (int e = threadIdx.x; e < 4096; e += 256) {
        float s = 0.f;
        #pragma unroll
        for (int ch = 0; ch < GC; ch++)
            s += g_Gpart[((size_t)((b * GC + ch) * 6 + tile)) * 4096 + e];
        int m = e >> 6, n = e & 63;
        Gb[(i0 + m) * C + j0 + n] = s;
        Gb[(j0 + n) * C + i0 + m] = s;
    }
}

// ---------------- K2a: T = Wq @ G ----------------
__global__ void k_qg(const float* __restrict__ wq) {
    int d0 = blockIdx.x * 64;
    int o0 = blockIdx.y * 64;
    int b  = blockIdx.z;

    __shared__ float Ws[64][68];
    __shared__ float Gs[64][68];

    int tid = threadIdx.x;
    int tx = tid & 15, ty = tid >> 4;
    float acc[4][4] = {};
    const float* Gb = g_G + (size_t)b * C * C;

    for (int c0 = 0; c0 < C; c0 += 64) {
        #pragma unroll
        for (int l = 0; l < 16; l++) {
            int idx = tid + l * 256;
            int r = idx >> 6, q = idx & 63;
            Ws[r][q] = wq[(o0 + r) * C + c0 + q];
            Gs[r][q] = Gb[(c0 + r) * C + d0 + q];
        }
        __syncthreads();
        #pragma unroll 16
        for (int c = 0; c < 64; c++) {
            float4 gv = *reinterpret_cast<const float4*>(&Gs[c][tx * 4]);
            float w0 = Ws[ty * 4 + 0][c], w1 = Ws[ty * 4 + 1][c];
            float w2 = Ws[ty * 4 + 2][c], w3 = Ws[ty * 4 + 3][c];
            acc[0][0] += w0 * gv.x; acc[0][1] += w0 * gv.y; acc[0][2] += w0 * gv.z; acc[0][3] += w0 * gv.w;
            acc[1][0] += w1 * gv.x; acc[1][1] += w1 * gv.y; acc[1][2] += w1 * gv.z; acc[1][3] += w1 * gv.w;
            acc[2][0] += w2 * gv.x; acc[2][1] += w2 * gv.y; acc[2][2] += w2 * gv.z; acc[2][3] += w2 * gv.w;
            acc[3][0] += w3 * gv.x; acc[3][1] += w3 * gv.y; acc[3][2] += w3 * gv.z; acc[3][3] += w3 * gv.w;
        }
        __syncthreads();
    }
    float* Tb = g_T + (size_t)b * INNER * C;
    #pragma unroll
    for (int ii = 0; ii < 4; ii++)
        #pragma unroll
        for (int jj = 0; jj < 4; jj++)
            Tb[(o0 + ty * 4 + ii) * C + d0 + tx * 4 + jj] = acc[ii][jj];
}

// ---------------- K2b: sim + softmax ----------------
__global__ void k_sim_softmax(const float* __restrict__ wk) {
    int n = blockIdx.x, b = blockIdx.y;
    __shared__ float buf[2 * 64 * 68];
    float (*Ts)[68] = (float (*)[68])buf;
    float (*Ks)[68] = (float (*)[68])(buf + 64 * 68);

    int tid = threadIdx.x;
    int tx = tid & 15, ty = tid >> 4;
    float acc[4][4] = {};

    const float* Tb = g_T + ((size_t)b * INNER + (size_t)n * DH) * C;
    const float* Kb = wk + (size_t)n * DH * C;

    for (int d0 = 0; d0 < C; d0 += 64) {
        #pragma unroll
        for (int l = 0; l < 16; l++) {
            int idx = tid + l * 256;
            int r = idx >> 6, q = idx & 63;
            Ts[r][q] = Tb[r * C + d0 + q];
            Ks[r][q] = Kb[r * C + d0 + q];
        }
        __syncthreads();
        #pragma unroll 4
        for (int s = 0; s < 64; s += 4) {
            float4 av[4], bv[4];
            #pragma unroll
            for (int k = 0; k < 4; k++) {
                av[k] = *reinterpret_cast<const float4*>(&Ts[ty * 4 + k][s]);
                bv[k] = *reinterpret_cast<const float4*>(&Ks[tx + 16 * k][s]);
            }
            #pragma unroll
            for (int ii = 0; ii < 4; ii++)
                #pragma unroll
                for (int jj = 0; jj < 4; jj++)
                    acc[ii][jj] += av[ii].x * bv[jj].x + av[ii].y * bv[jj].y
                                 + av[ii].z * bv[jj].z + av[ii].w * bv[jj].w;
        }
        __syncthreads();
    }

    float (*sims)[65] = (float (*)[65])buf;
    #pragma unroll
    for (int ii = 0; ii < 4; ii++)
        #pragma unroll
        for (int jj = 0; jj < 4; jj++)
            sims[ty * 4 + ii][tx + 16 * jj] = acc[ii][jj] * ATT_SCALE;
    __syncthreads();

    int w = tid >> 5, lane = tid & 31;
    for (int r = w; r < 64; r += 8) {
        float m = fmaxf(sims[r][lane], sims[r][lane + 32]);
        #pragma unroll
        for (int off = 16; off; off >>= 1)
            m = fmaxf(m, __shfl_xor_sync(0xffffffffu, m, off));
        float e0 = __expf(sims[r][lane] - m);
        float e1 = __expf(sims[r][lane + 32] - m);
        float sum = e0 + e1;
        #pragma unroll
        for (int off = 16; off; off >>= 1)
            sum += __shfl_xor_sync(0xffffffffu, sum, off);
        float inv = 1.f / sum;
        float* arow = g_attn + (((size_t)(b * NH + n)) * DH + r) * DH;
        arow[lane]      = e0 * inv;
        arow[lane + 32] = e1 * inv;
    }
}

// ---------------- K3a: AV = blockdiag(attn) @ Wv ----------------
__global__ void k_av(const float* __restrict__ wv) {
    int c0 = blockIdx.x * 64;
    int n  = blockIdx.y;
    int b  = blockIdx.z;

    __shared__ float Asm[64][68];
    __shared__ float Vs[64][68];

    int tid = threadIdx.x;
    int tx = tid & 15, ty = tid >> 4;

    #pragma unroll
    for (int l = 0; l < 16; l++) {
        int idx = tid + l * 256;
        int r = idx >> 6, q = idx & 63;
        Asm[r][q] = g_attn[(((size_t)(b * NH + n)) * DH + r) * DH + q];
        Vs[r][q]  = wv[(n * DH + r) * C + c0 + q];
    }
    __syncthreads();

    float acc[4][4] = {};
    #pragma unroll 16
    for (int j = 0; j < 64; j++) {
        float4 vv = *reinterpret_cast<const float4*>(&Vs[j][tx * 4]);
        float a0 = Asm[ty * 4 + 0][j], a1 = Asm[ty * 4 + 1][j];
        float a2 = Asm[ty * 4 + 2][j], a3 = Asm[ty * 4 + 3][j];
        acc[0][0] += a0 * vv.x; acc[0][1] += a0 * vv.y; acc[0][2] += a0 * vv.z; acc[0][3] += a0 * vv.w;
        acc[1][0] += a1 * vv.x; acc[1][1] += a1 * vv.y; acc[1][2] += a1 * vv.z; acc[1][3] += a1 * vv.w;
        acc[2][0] += a2 * vv.x; acc[2][1] += a2 * vv.y; acc[2][2] += a2 * vv.z; acc[2][3] += a2 * vv.w;
        acc[3][0] += a3 * vv.x; acc[3][1] += a3 * vv.y; acc[3][2] += a3 * vv.z; acc[3][3] += a3 * vv.w;
    }
    #pragma unroll
    for (int ii = 0; ii < 4; ii++)
        #pragma unroll
        for (int jj = 0; jj < 4; jj++)
            g_AV[((size_t)b * INNER + n * DH + ty * 4 + ii) * C + c0 + tx * 4 + jj] = acc[ii][jj];
}

// ---------------- K3b: M = Wo @ AV ----------------
__global__ void k_m(const float* __restrict__ wo) {
    int c0 = blockIdx.x * 64;
    int o0 = (blockIdx.y % 3) * 64;
    int kc = blockIdx.y / 3;
    int b  = blockIdx.z;

    __shared__ float Ws[64][68];
    __shared__ float Vs[64][68];

    int tid = threadIdx.x;
    int tx = tid & 15, ty = tid >> 4;
    float acc[4][4] = {};

    for (int kk = 0; kk < 128; kk += 64) {
        int k0 = kc * 128 + kk;
        #pragma unroll
        for (int l = 0; l < 16; l++) {
            int idx = tid + l * 256;
            int r = idx >> 6, q = idx & 63;
            Ws[r][q] = wo[(o0 + r) * INNER + k0 + q];
            Vs[r][q] = g_AV[((size_t)b * INNER + k0 + r) * C + c0 + q];
        }
        __syncthreads();
        #pragma unroll 16
        for (int k = 0; k < 64; k++) {
            float4 vv = *reinterpret_cast<const float4*>(&Vs[k][tx * 4]);
            float w0 = Ws[ty * 4 + 0][k], w1 = Ws[ty * 4 + 1][k];
            float w2 = Ws[ty * 4 + 2][k], w3 = Ws[ty * 4 + 3][k];
            acc[0][0] += w0 * vv.x; acc[0][1] += w0 * vv.y; acc[0][2] += w0 * vv.z; acc[0][3] += w0 * vv.w;
            acc[1][0] += w1 * vv.x; acc[1][1] += w1 * vv.y; acc[1][2] += w1 * vv.z; acc[1][3] += w1 * vv.w;
            acc[2][0] += w2 * vv.x; acc[2][1] += w2 * vv.y; acc[2][2] += w2 * vv.z; acc[2][3] += w2 * vv.w;
            acc[3][0] += w3 * vv.x; acc[3][1] += w3 * vv.y; acc[3][2] += w3 * vv.z; acc[3][3] += w3 * vv.w;
        }
        __syncthreads();
    }
    float* Mp = g_Mpart + ((size_t)(b * 4 + kc)) * C * C;
    #pragma unroll
    for (int ii = 0; ii < 4; ii++)
        #pragma unroll
        for (int jj = 0; jj < 4; jj++)
            Mp[(o0 + ty * 4 + ii) * C + tx * 4 + jj + c0] = acc[ii][jj];
}

__global__ void k_m_reduce() {
    int b = blockIdx.y;
    int e = blockIdx.x * 256 + threadIdx.x;
    if (e < C * C) {
        float s = 0.f;
        #pragma unroll
        for (int kc = 0; kc < 4; kc++)
            s += g_Mpart[((size_t)(b * 4 + kc)) * C * C + e];
        g_M[(size_t)b * C * C + e] = s;
    }
}

// ============ K4: out = M @ X + bo (ldmatrix.trans + 2-stage double buffer) ============
// sM per stage: [2 splits][64][MPAD] (k-major), sX: [2 splits][32][SPAD] (k-major rows, s cols)
#define MPAD 40    // 80B rows = 5 x 16B
#define SPAD 136   // 272B rows = 17 x 16B
#define O_M_BYTES     (2 * 64 * MPAD * 2)   // 10240
#define O_X_BYTES     (2 * 32 * SPAD * 2)   // 17408
#define O_M_SPLIT_OFF (64 * MPAD)
#define O_X_SPLIT_OFF (32 * SPAD)
#define O_STAGE       (O_M_BYTES + O_X_BYTES)  // 27648
#define O_SMEM        (2 * O_STAGE)            // 55296

__global__ void __launch_bounds__(256, 2) k_out(const float* __restrict__ x,
                                                const float* __restrict__ bo,
                                                float* __restrict__ out) {
    extern __shared__ char dyn[];
    int s0blk = blockIdx.x * 128;
    int o0 = blockIdx.y * 64;
    int b  = blockIdx.z;

    int tid  = threadIdx.x;
    int w    = tid >> 5, lane = tid & 31;
    int grp  = lane >> 2, tig = lane & 3;
    int wm   = w & 1, wn = w >> 1;
    int rsel = lane & 15, csel = (lane >> 4) << 3;

    const float* xb = x + (size_t)b * C * S;
    const float* Mb = g_M + (size_t)b * C * C;

    float acc[2][4][4] = {};

    int mr = tid >> 3, mc = (tid & 7) * 4;      // M: rows mr, mr+32; cols mc..mc+3
    int xk = tid >> 3, xs = (tid & 7) * 16;     // X: k-row xk; s cols xs..xs+15

    float4 pm[2], px[4];
    pm[0] = *reinterpret_cast<const float4*>(&Mb[(o0 + mr) * C + mc]);
    pm[1] = *reinterpret_cast<const float4*>(&Mb[(o0 + mr + 32) * C + mc]);
    #pragma unroll
    for (int i = 0; i < 4; i++)
        px[i] = *reinterpret_cast<const float4*>(&xb[(size_t)xk * S + s0blk + xs + i * 4]);

    // convert chunk 0 into stage 0
    {
        __nv_bfloat16* sM = (__nv_bfloat16*)(dyn);
        __nv_bfloat16* sX = (__nv_bfloat16*)(dyn + O_M_BYTES);
        #pragma unroll
        for (int i = 0; i < 2; i++) {
            uint32_t h0, l0, h1, l1;
            split_pack(pm[i].x, pm[i].y, h0, l0);
            split_pack(pm[i].z, pm[i].w, h1, l1);
            int base = (mr + i * 32) * MPAD + mc;
            *reinterpret_cast<uint2*>(&sM[base])                 = make_uint2(h0, h1);
            *reinterpret_cast<uint2*>(&sM[O_M_SPLIT_OFF + base]) = make_uint2(l0, l1);
        }
        #pragma unroll
        for (int i = 0; i < 4; i++) {
            uint32_t h0, l0, h1, l1;
            split_pack(px[i].x, px[i].y, h0, l0);
            split_pack(px[i].z, px[i].w, h1, l1);
            int base = xk * SPAD + xs + i * 4;
            *reinterpret_cast<uint2*>(&sX[base])                 = make_uint2(h0, h1);
            *reinterpret_cast<uint2*>(&sX[O_X_SPLIT_OFF + base]) = make_uint2(l0, l1);
        }
    }
    __syncthreads();

    #pragma unroll 1
    for (int it = 0; it < 6; it++) {
        int cur = it & 1;
        bool more = (it < 5);

        if (more) {
            int kc = (it + 1) * 32;
            pm[0] = *reinterpret_cast<const float4*>(&Mb[(o0 + mr) * C + kc + mc]);
            pm[1] = *reinterpret_cast<const float4*>(&Mb[(o0 + mr + 32) * C + kc + mc]);
            #pragma unroll
            for (int i = 0; i < 4; i++)
                px[i] = *reinterpret_cast<const float4*>(&xb[(size_t)(kc + xk) * S + s0blk + xs + i * 4]);
        }

        uint32_t sMu = s2u(dyn + cur * O_STAGE);
        uint32_t sXu = sMu + O_M_BYTES;
        #pragma unroll
        for (int ks = 0; ks < 2; ks++) {
            int kb = ks * 16;
            uint32_t a[2][2][4];
            #pragma unroll
            for (int h = 0; h < 2; h++)
                #pragma unroll
                for (int mf = 0; mf < 2; mf++) {
                    uint32_t addr = sMu + 2 * (h * O_M_SPLIT_OFF + (wm * 32 + mf * 16 + rsel) * MPAD + kb + csel);
                    LDSM4(a[h][mf][0], a[h][mf][1], a[h][mf][2], a[h][mf][3], addr);
                }
            uint32_t bb[2][4][2];
            #pragma unroll
            for (int h = 0; h < 2; h++)
                #pragma unroll
                for (int nfp = 0; nfp < 2; nfp++) {
                    int scol = wn * 32 + nfp * 16;
                    uint32_t addr = sXu + 2 * (h * O_X_SPLIT_OFF + (kb + rsel) * SPAD + scol + csel);
                    uint32_t r0, r1, r2, r3;
                    LDSM4T(r0, r1, r2, r3, addr);
                    bb[h][nfp * 2][0] = r0; bb[h][nfp * 2][1] = r1;
                    bb[h][nfp * 2 + 1][0] = r2; bb[h][nfp * 2 + 1][1] = r3;
                }
            #pragma unroll
            for (int mf = 0; mf < 2; mf++)
                #pragma unroll
                for (int nf = 0; nf < 4; nf++) {
                    mma2(acc[mf][nf], a[0][mf][0], a[0][mf][1], a[0][mf][2], a[0][mf][3], bb[0][nf][0], bb[0][nf][1]);
                    mma2(acc[mf][nf], a[0][mf][0], a[0][mf][1], a[0][mf][2], a[0][mf][3], bb[1][nf][0], bb[1][nf][1]);
                    mma2(acc[mf][nf], a[1][mf][0], a[1][mf][1], a[1][mf][2], a[1][mf][3], bb[0][nf][0], bb[0][nf][1]);
                }
        }

        if (more) {
            __nv_bfloat16* sM = (__nv_bfloat16*)(dyn + (cur ^ 1) * O_STAGE);
            __nv_bfloat16* sX = (__nv_bfloat16*)(dyn + (cur ^ 1) * O_STAGE + O_M_BYTES);
            #pragma unroll
            for (int i = 0; i < 2; i++) {
                uint32_t h0, l0, h1, l1;
                split_pack(pm[i].x, pm[i].y, h0, l0);
                split_pack(pm[i].z, pm[i].w, h1, l1);
                int base = (mr + i * 32) * MPAD + mc;
                *reinterpret_cast<uint2*>(&sM[base])                 = make_uint2(h0, h1);
                *reinterpret_cast<uint2*>(&sM[O_M_SPLIT_OFF + base]) = make_uint2(l0, l1);
            }
            #pragma unroll
            for (int i = 0; i < 4; i++) {
                uint32_t h0, l0, h1, l1;
                split_pack(px[i].x, px[i].y, h0, l0);
                split_pack(px[i].z, px[i].w, h1, l1);
                int base = xk * SPAD + xs + i * 4;
                *reinterpret_cast<uint2*>(&sX[base])                 = make_uint2(h0, h1);
                *reinterpret_cast<uint2*>(&sX[O_X_SPLIT_OFF + base]) = make_uint2(l0, l1);
            }
        }
        __syncthreads();
    }

    #pragma unroll
    for (int mf = 0; mf < 2; mf++) {
        int row0 = o0 + wm * 32 + mf * 16 + grp;
        float bias0 = bo[row0];
        float bias1 = bo[row0 + 8];
        #pragma unroll
        for (int nf = 0; nf < 4; nf++) {
            int col = s0blk + wn * 32 + nf * 8 + tig * 2;
            *reinterpret_cast<float2*>(&out[((size_t)b * C + row0) * S + col]) =
                make_float2(acc[mf][nf][0] + bias0, acc[mf][nf][1] + bias0);
            *reinterpret_cast<float2*>(&out[((size_t)b * C + row0 + 8) * S + col]) =
                make_float2(acc[mf][nf][2] + bias1, acc[mf][nf][3] + bias1);
        }
    }
}

// ---------------- launch ----------------
extern "C" void kernel_launch(void* const* d_in, const int* in_sizes, int n_in,
                              void* d_out, int out_size) {
    const float* x  = (const float*)d_in[0];
    const float* wq = (const float*)d_in[1];
    const float* wk = (const float*)d_in[2];
    const float* wv = (const float*)d_in[3];
    const float* wo = (const float*)d_in[4];
    const float* bo = (const float*)d_in[5];
    float* out = (float*)d_out;

    cudaFuncSetAttribute(k_gram, cudaFuncAttributeMaxDynamicSharedMemorySize, G_SMEM);
    cudaFuncSetAttribute(k_out,  cudaFuncAttributeMaxDynamicSharedMemorySize, O_SMEM);

    k_gram<<<dim3(6, GC, BATCH), 256, G_SMEM>>>(x);
    k_gram_reduce<<<dim3(6, BATCH), 256>>>();
    k_qg<<<dim3(3, 8, BATCH), 256>>>(wq);
    k_sim_softmax<<<dim3(NH, BATCH), 256>>>(wk);
    k_av<<<dim3(3, NH, BATCH), 256>>>(wv);
    k_m<<<dim3(3, 12, BATCH), 256>>>(wo);
    k_m_reduce<<<dim3(144, BATCH), 256>>>();
    k_out<<<dim3(S / 128, 3, BATCH), 256, O_SMEM>>>(x, bo, out);
}